// round 14
// baseline (speedup 1.0000x reference)
#include <cuda_runtime.h>
#include <cuda_bf16.h>
#include <math.h>
#include <cstdint>

#define TT   2048
#define HID  2048
#define NH   16
#define NKV  8
#define HD   128
#define QS   (NH * HD)          // 2048
#define KVS  (NKV * HD)         // 1024
#define QKVN (QS + 2 * KVS)     // 4096

// ---------------- scratch (__device__ globals; allocation-free rule) --------
__device__ float g_qkv[TT * QKVN];            // 32 MB
__device__ __nv_bfloat16 g_hid_h[TT * HID];
__device__ __nv_bfloat16 g_hid_l[TT * HID];
__device__ __nv_bfloat16 g_qkvw_h[QKVN * HID];
__device__ __nv_bfloat16 g_qkvw_l[QKVN * HID];
__device__ __nv_bfloat16 g_ow_h[HID * QS];
__device__ __nv_bfloat16 g_ow_l[HID * QS];
__device__ __nv_bfloat16 g_ctx_h[TT * QS];
__device__ __nv_bfloat16 g_ctx_l[TT * QS];
__device__ __nv_bfloat16 g_qh[TT * QS];
__device__ __nv_bfloat16 g_ql[TT * QS];
__device__ __nv_bfloat16 g_kh[TT * KVS];
__device__ __nv_bfloat16 g_kl[TT * KVS];
__device__ __nv_bfloat16 g_vh[TT * KVS];
__device__ __nv_bfloat16 g_vl[TT * KVS];

// ---------------- helpers -----------------------------------------------------
__device__ __forceinline__ uint32_t smem_u32(const void* p) {
    uint32_t a;
    asm("{ .reg .u64 t; cvta.to.shared.u64 t, %1; cvt.u32.u64 %0, t; }" : "=r"(a) : "l"(p));
    return a;
}

__device__ __forceinline__ void cpa16(uint32_t s, const void* g) {
    asm volatile("cp.async.cg.shared.global [%0], [%1], 16;" :: "r"(s), "l"(g));
}
#define CP_COMMIT() asm volatile("cp.async.commit_group;" ::: "memory")
#define CP_WAIT1()  asm volatile("cp.async.wait_group 1;" ::: "memory")
#define CP_WAIT0()  asm volatile("cp.async.wait_group 0;" ::: "memory")

__device__ __forceinline__ void ldmx4(uint32_t* r, uint32_t addr) {
    asm volatile("ldmatrix.sync.aligned.m8n8.x4.shared.b16 {%0,%1,%2,%3}, [%4];"
                 : "=r"(r[0]), "=r"(r[1]), "=r"(r[2]), "=r"(r[3]) : "r"(addr));
}
__device__ __forceinline__ void ldmx4t(uint32_t* r, uint32_t addr) {
    asm volatile("ldmatrix.sync.aligned.m8n8.x4.trans.shared.b16 {%0,%1,%2,%3}, [%4];"
                 : "=r"(r[0]), "=r"(r[1]), "=r"(r[2]), "=r"(r[3]) : "r"(addr));
}

__device__ __forceinline__ void mma16816(float* d, const uint32_t* a,
                                         uint32_t b0, uint32_t b1) {
    asm volatile(
        "mma.sync.aligned.m16n8k16.row.col.f32.bf16.bf16.f32 "
        "{%0,%1,%2,%3}, {%4,%5,%6,%7}, {%8,%9}, {%0,%1,%2,%3};"
        : "+f"(d[0]), "+f"(d[1]), "+f"(d[2]), "+f"(d[3])
        : "r"(a[0]), "r"(a[1]), "r"(a[2]), "r"(a[3]), "r"(b0), "r"(b1));
}

__device__ __forceinline__ uint32_t packbf(float lo, float hi) {
    uint32_t r;
    asm("cvt.rn.bf16x2.f32 %0, %1, %2;" : "=r"(r) : "f"(hi), "f"(lo));
    return r;
}

__device__ __forceinline__ float ex2f(float x) {
    float y; asm("ex2.approx.f32 %0, %1;" : "=f"(y) : "f"(x)); return y;
}

// packed swizzled 64B-row tile (gemm): row r (0..127), 16B chunk c (0..3)
__device__ __forceinline__ uint32_t sw64(uint32_t row, uint32_t c16) {
    uint32_t line = row >> 1;
    uint32_t slot = (((row & 1) << 2) + c16) ^ (line & 7);
    return (line << 7) + (slot << 4);
}
// packed 64-row x 256B tile (attention KV)
__device__ __forceinline__ uint32_t swkv(uint32_t row, uint32_t c16) {
    return ((c16 >> 3) << 13) + (row << 7) + (((c16 & 7) ^ (row & 7)) << 4);
}
// packed 128-row x 256B tile (attention Q)
__device__ __forceinline__ uint32_t swq(uint32_t row, uint32_t c16) {
    return ((c16 >> 3) << 14) + (row << 7) + (((c16 & 7) ^ (row & 7)) << 4);
}

// ---------------- fused fp32 -> bf16 hi/lo split over 3 arrays -----------------
#define N4_HID  (TT * HID / 4)            // 1M
#define N4_QW   (QKVN * HID / 4)          // 2M
#define N4_OW   (HID * QS / 4)            // 1M

__global__ __launch_bounds__(256) void split_all(
    const float* __restrict__ hid, const float* __restrict__ qw,
    const float* __restrict__ ow,
    __nv_bfloat16* __restrict__ hid_h, __nv_bfloat16* __restrict__ hid_l,
    __nv_bfloat16* __restrict__ qw_h,  __nv_bfloat16* __restrict__ qw_l,
    __nv_bfloat16* __restrict__ ow_h,  __nv_bfloat16* __restrict__ ow_l)
{
    int i = blockIdx.x * 256 + threadIdx.x;
    const float* x; __nv_bfloat16* h; __nv_bfloat16* l;
    if (i < N4_HID)              { x = hid; h = hid_h; l = hid_l; }
    else if (i < N4_HID + N4_QW) { i -= N4_HID; x = qw; h = qw_h; l = qw_l; }
    else                         { i -= N4_HID + N4_QW; x = ow; h = ow_h; l = ow_l; }
    float4 v = ((const float4*)x)[i];
    __nv_bfloat16 h0 = __float2bfloat16_rn(v.x);
    __nv_bfloat16 h1 = __float2bfloat16_rn(v.y);
    __nv_bfloat16 h2 = __float2bfloat16_rn(v.z);
    __nv_bfloat16 h3 = __float2bfloat16_rn(v.w);
    __nv_bfloat16 l0 = __float2bfloat16_rn(v.x - __bfloat162float(h0));
    __nv_bfloat16 l1 = __float2bfloat16_rn(v.y - __bfloat162float(h1));
    __nv_bfloat16 l2 = __float2bfloat16_rn(v.z - __bfloat162float(h2));
    __nv_bfloat16 l3 = __float2bfloat16_rn(v.w - __bfloat162float(h3));
    ((ushort4*)h)[i] = make_ushort4(__bfloat16_as_ushort(h0), __bfloat16_as_ushort(h1),
                                    __bfloat16_as_ushort(h2), __bfloat16_as_ushort(h3));
    ((ushort4*)l)[i] = make_ushort4(__bfloat16_as_ushort(l0), __bfloat16_as_ushort(l1),
                                    __bfloat16_as_ushort(l2), __bfloat16_as_ushort(l3));
}

// ---------------- HMMA bf16x3 GEMM (R8 winner, exact) -------------------------
#define TILE_B  8192
#define STAGE_B (4 * TILE_B)
#define DSMEM_B (3 * STAGE_B)

__global__ __launch_bounds__(256, 2) void gemm_mma(
    const __nv_bfloat16* __restrict__ Ah, const __nv_bfloat16* __restrict__ Al,
    const __nv_bfloat16* __restrict__ Bh, const __nv_bfloat16* __restrict__ Bl,
    float* __restrict__ C, int M, int N, int K)
{
    extern __shared__ char sal[];
    const int tid  = threadIdx.x;
    const int wid  = tid >> 5;
    const int lane = tid & 31;
    const int wm   = wid & 3;
    const int wn   = wid >> 2;
    const int bm = blockIdx.y * 128;
    const int bn = blockIdx.x * 128;
    const int NC = K >> 5;

    const uint32_t sb = smem_u32(sal);

    const int r0 = tid >> 2;
    const int c0 = tid & 3;
    const size_t ga = (size_t)(bm + r0) * K + c0 * 8;
    const size_t gb = (size_t)(bn + r0) * K + c0 * 8;
    const uint32_t so_a = sw64((uint32_t)r0, (uint32_t)c0);
    const uint32_t so_b = sw64((uint32_t)(r0 + 64), (uint32_t)c0);

    const uint32_t arow = (uint32_t)(wm * 32 + (lane & 15));
    const uint32_t ac   = (uint32_t)(lane >> 4);
    const uint32_t brow = (uint32_t)(wn * 64 + (lane & 7) + ((lane >> 4) << 3));
    const uint32_t bc   = (uint32_t)((lane >> 3) & 1);

    float acc[2][8][4];
#pragma unroll
    for (int i = 0; i < 2; i++)
#pragma unroll
        for (int j = 0; j < 8; j++)
#pragma unroll
            for (int q = 0; q < 4; q++) acc[i][j][q] = 0.f;

#pragma unroll
    for (int pc = 0; pc < 2; pc++) {
        const size_t kk0 = (size_t)pc << 5;
        const uint32_t st = sb + pc * STAGE_B;
        cpa16(st + 0 * TILE_B + so_a, Ah + ga + kk0);
        cpa16(st + 0 * TILE_B + so_b, Ah + ga + kk0 + 64 * K);
        cpa16(st + 1 * TILE_B + so_a, Al + ga + kk0);
        cpa16(st + 1 * TILE_B + so_b, Al + ga + kk0 + 64 * K);
        cpa16(st + 2 * TILE_B + so_a, Bh + gb + kk0);
        cpa16(st + 2 * TILE_B + so_b, Bh + gb + kk0 + 64 * K);
        cpa16(st + 3 * TILE_B + so_a, Bl + gb + kk0);
        cpa16(st + 3 * TILE_B + so_b, Bl + gb + kk0 + 64 * K);
        CP_COMMIT();
    }

    int cs = 0;
    for (int c = 0; c < NC; c++) {
        if (c == NC - 1) { CP_WAIT0(); } else { CP_WAIT1(); }
        __syncthreads();

        if (c + 2 < NC) {
            int ws = cs + 2; if (ws >= 3) ws -= 3;
            const size_t kk0 = (size_t)(c + 2) << 5;
            const uint32_t st = sb + ws * STAGE_B;
            cpa16(st + 0 * TILE_B + so_a, Ah + ga + kk0);
            cpa16(st + 0 * TILE_B + so_b, Ah + ga + kk0 + 64 * K);
            cpa16(st + 1 * TILE_B + so_a, Al + ga + kk0);
            cpa16(st + 1 * TILE_B + so_b, Al + ga + kk0 + 64 * K);
            cpa16(st + 2 * TILE_B + so_a, Bh + gb + kk0);
            cpa16(st + 2 * TILE_B + so_b, Bh + gb + kk0 + 64 * K);
            cpa16(st + 3 * TILE_B + so_a, Bl + gb + kk0);
            cpa16(st + 3 * TILE_B + so_b, Bl + gb + kk0 + 64 * K);
            CP_COMMIT();
        }

        const uint32_t sAh = sb + cs * STAGE_B;
        const uint32_t sAl = sAh + TILE_B;
        const uint32_t sBh = sAh + 2 * TILE_B;
        const uint32_t sBl = sAh + 3 * TILE_B;

#pragma unroll
        for (int kk = 0; kk < 2; kk++) {
            const uint32_t ac16 = ac + kk * 2;
            const uint32_t bc16 = bc + kk * 2;
            uint32_t ah[2][4], al[2][4];
            ldmx4(ah[0], sAh + sw64(arow,      ac16));
            ldmx4(ah[1], sAh + sw64(arow + 16, ac16));
            ldmx4(al[0], sAl + sw64(arow,      ac16));
            ldmx4(al[1], sAl + sw64(arow + 16, ac16));
#pragma unroll
            for (int np = 0; np < 2; np++) {
                const int nt0 = 2 * np, nt1 = 2 * np + 1;
                uint32_t b0h[4], b1h[4], b0l[4], b1l[4];
                ldmx4(b0h, sBh + sw64(brow + nt0 * 16, bc16));
                ldmx4(b1h, sBh + sw64(brow + nt1 * 16, bc16));
                ldmx4(b0l, sBl + sw64(brow + nt0 * 16, bc16));
                ldmx4(b1l, sBl + sw64(brow + nt1 * 16, bc16));
                mma16816(acc[0][2 * nt0],     ah[0], b0h[0], b0h[1]);
                mma16816(acc[0][2 * nt0 + 1], ah[0], b0h[2], b0h[3]);
                mma16816(acc[1][2 * nt0],     ah[1], b0h[0], b0h[1]);
                mma16816(acc[1][2 * nt0 + 1], ah[1], b0h[2], b0h[3]);
                mma16816(acc[0][2 * nt1],     ah[0], b1h[0], b1h[1]);
                mma16816(acc[0][2 * nt1 + 1], ah[0], b1h[2], b1h[3]);
                mma16816(acc[1][2 * nt1],     ah[1], b1h[0], b1h[1]);
                mma16816(acc[1][2 * nt1 + 1], ah[1], b1h[2], b1h[3]);
                mma16816(acc[0][2 * nt0],     ah[0], b0l[0], b0l[1]);
                mma16816(acc[0][2 * nt0 + 1], ah[0], b0l[2], b0l[3]);
                mma16816(acc[1][2 * nt0],     ah[1], b0l[0], b0l[1]);
                mma16816(acc[1][2 * nt0 + 1], ah[1], b0l[2], b0l[3]);
                mma16816(acc[0][2 * nt1],     ah[0], b1l[0], b1l[1]);
                mma16816(acc[0][2 * nt1 + 1], ah[0], b1l[2], b1l[3]);
                mma16816(acc[1][2 * nt1],     ah[1], b1l[0], b1l[1]);
                mma16816(acc[1][2 * nt1 + 1], ah[1], b1l[2], b1l[3]);
                mma16816(acc[0][2 * nt0],     al[0], b0h[0], b0h[1]);
                mma16816(acc[0][2 * nt0 + 1], al[0], b0h[2], b0h[3]);
                mma16816(acc[1][2 * nt0],     al[1], b0h[0], b0h[1]);
                mma16816(acc[1][2 * nt0 + 1], al[1], b0h[2], b0h[3]);
                mma16816(acc[0][2 * nt1],     al[0], b1h[0], b1h[1]);
                mma16816(acc[0][2 * nt1 + 1], al[0], b1h[2], b1h[3]);
                mma16816(acc[1][2 * nt1],     al[1], b1h[0], b1h[1]);
                mma16816(acc[1][2 * nt1 + 1], al[1], b1h[2], b1h[3]);
            }
        }
        if (++cs >= 3) cs = 0;
    }

    const int mr = bm + wm * 32 + (lane >> 2);
    const int nc0 = bn + wn * 64 + (lane & 3) * 2;
#pragma unroll
    for (int mt = 0; mt < 2; mt++) {
#pragma unroll
        for (int n8 = 0; n8 < 8; n8++) {
            int row = mr + mt * 16;
            int col = nc0 + n8 * 8;
            *(float2*)(C + (size_t)row * N + col) =
                make_float2(acc[mt][n8][0], acc[mt][n8][1]);
            *(float2*)(C + (size_t)(row + 8) * N + col) =
                make_float2(acc[mt][n8][2], acc[mt][n8][3]);
        }
    }
}

// ---------------- fused RMSNorm+RoPE (Q/K) and V split ------------------------
// grid (T, 26): hh<24 -> norm+rope head; hh 24,25 -> V split halves
__global__ __launch_bounds__(128) void norm_rope_v(
    const float* __restrict__ qkv, const int* __restrict__ pos,
    const float* __restrict__ qw,  const float* __restrict__ kw,
    __nv_bfloat16* __restrict__ qh, __nv_bfloat16* __restrict__ ql,
    __nv_bfloat16* __restrict__ kh, __nv_bfloat16* __restrict__ kl,
    __nv_bfloat16* __restrict__ vh, __nv_bfloat16* __restrict__ vl)
{
    const int t  = blockIdx.x;
    const int hh = blockIdx.y;
    const int d  = threadIdx.x;

    if (hh >= NH + NKV) {     // V split: 2 blocks x 128 threads x 4 floats = 1024
        int i = ((hh - NH - NKV) * 128 + d) * 4;
        float4 v = *(const float4*)(qkv + (size_t)t * QKVN + QS + KVS + i);
        __nv_bfloat16 h0 = __float2bfloat16_rn(v.x);
        __nv_bfloat16 h1 = __float2bfloat16_rn(v.y);
        __nv_bfloat16 h2 = __float2bfloat16_rn(v.z);
        __nv_bfloat16 h3 = __float2bfloat16_rn(v.w);
        __nv_bfloat16 l0 = __float2bfloat16_rn(v.x - __bfloat162float(h0));
        __nv_bfloat16 l1 = __float2bfloat16_rn(v.y - __bfloat162float(h1));
        __nv_bfloat16 l2 = __float2bfloat16_rn(v.z - __bfloat162float(h2));
        __nv_bfloat16 l3 = __float2bfloat16_rn(v.w - __bfloat162float(h3));
        size_t o = (size_t)t * KVS + i;
        *(ushort4*)(vh + o) = make_ushort4(__bfloat16_as_ushort(h0), __bfloat16_as_ushort(h1),
                                           __bfloat16_as_ushort(h2), __bfloat16_as_ushort(h3));
        *(ushort4*)(vl + o) = make_ushort4(__bfloat16_as_ushort(l0), __bfloat16_as_ushort(l1),
                                           __bfloat16_as_ushort(l2), __bfloat16_as_ushort(l3));
        return;
    }

    const float* src; const float* w;
    __nv_bfloat16* dsth; __nv_bfloat16* dstl; size_t dofs;
    bool isq = (hh < NH);
    if (isq) {
        src = qkv + (size_t)t * QKVN + hh * HD;
        w = qw;
        dsth = qh; dstl = ql;
        dofs = ((size_t)t * NH + hh) * HD + d;
    } else {
        int khd = hh - NH;
        src = qkv + (size_t)t * QKVN + QS + khd * HD;
        w = kw;
        dsth = kh; dstl = kl;
        dofs = ((size_t)t * NKV + khd) * HD + d;
    }

    float x = src[d];
    float ss = x * x;
#pragma unroll
    for (int o = 16; o > 0; o >>= 1)
        ss += __shfl_xor_sync(0xffffffffu, ss, o);

    __shared__ float red[4];
    __shared__ float xs[128];
    if ((d & 31) == 0) red[d >> 5] = ss;
    __syncthreads();
    float ms = (red[0] + red[1] + red[2] + red[3]) * (1.f / 128.f);
    float xn = x * rsqrtf(ms + 1e-6f) * w[d];
    xs[d] = xn;
    __syncthreads();

    float p = (float)pos[t];
    int i = d & 63;
    float freq = p * exp2f((float)i * -0.2076205059304601f);
    float s, c;
    sincosf(freq, &s, &c);
    float other = (d < 64) ? xs[d + 64] : xs[d - 64];
    float val = (d < 64) ? (xn * c - other * s) : (xn * c + other * s);

    if (isq) val *= (0.088388347648318447f * 1.4426950408889634f);  // scale*log2e

    __nv_bfloat16 hv = __float2bfloat16_rn(val);
    dsth[dofs] = hv;
    dstl[dofs] = __float2bfloat16_rn(val - __bfloat162float(hv));
}

// ---------------- HMMA flash attention (R10 exact) -----------------------------
#define KVT    16384
#define ASTG   (4 * KVT)
#define AQOFF  (2 * ASTG)
#define ASMEM  (3 * ASTG)

__global__ __launch_bounds__(256, 1) void attn_mma(
    const __nv_bfloat16* __restrict__ Qh, const __nv_bfloat16* __restrict__ Ql,
    const __nv_bfloat16* __restrict__ Kh, const __nv_bfloat16* __restrict__ Kl,
    const __nv_bfloat16* __restrict__ Vh, const __nv_bfloat16* __restrict__ Vl,
    __nv_bfloat16* __restrict__ cxh, __nv_bfloat16* __restrict__ cxl)
{
    extern __shared__ char sm[];
    const int h   = blockIdx.y;
    const int kvh = h >> 1;
    const int q0  = (int)(gridDim.x - 1 - blockIdx.x) * 128;
    const int tid = threadIdx.x;
    const int w   = tid >> 5;
    const int lane = tid & 31;

    const uint32_t sb = smem_u32(sm);
    const int ntile = (q0 >> 6) + 2;

    const int sub  = tid >> 6;
    const int lrow = tid & 63;
    const __nv_bfloat16* lsrc = (sub == 0) ? Kh : (sub == 1) ? Kl
                              : (sub == 2) ? Vh : Vl;
    const uint32_t lso = (uint32_t)(sub * KVT);
    const size_t lg = (size_t)lrow * KVS + kvh * HD;

#pragma unroll
    for (int p = 0; p < 2; p++) {
        const uint32_t st = sb + p * ASTG + lso;
        const __nv_bfloat16* g = lsrc + lg + (size_t)(p * 64) * KVS;
#pragma unroll
        for (int ci = 0; ci < 16; ci++)
            cpa16(st + swkv((uint32_t)lrow, (uint32_t)ci), g + ci * 8);
        CP_COMMIT();
    }

    {
        const int part = tid >> 7, row = tid & 127;
        const __nv_bfloat16* src = (part ? Ql : Qh) + (size_t)(q0 + row) * QS + h * HD;
        char* d = sm + AQOFF + part * 32768;
#pragma unroll
        for (int ci = 0; ci < 16; ci++)
            *(uint4*)(d + swq((uint32_t)row, (uint32_t)ci)) = *(const uint4*)(src + ci * 8);
    }
    __syncthreads();

    uint32_t qfh[8][4], qfl[8][4];
    {
        const uint32_t arow = (uint32_t)(w * 16 + (lane & 15));
#pragma unroll
        for (int kk = 0; kk < 8; kk++) {
            uint32_t c16 = (uint32_t)(lane >> 4) + kk * 2;
            ldmx4(qfh[kk], sb + AQOFF + swq(arow, c16));
            ldmx4(qfl[kk], sb + AQOFF + 32768 + swq(arow, c16));
        }
    }

    float oacc[16][4];
#pragma unroll
    for (int n = 0; n < 16; n++)
#pragma unroll
        for (int q = 0; q < 4; q++) oacc[n][q] = 0.f;
    float m0 = -1e30f, m1 = -1e30f, l0 = 0.f, l1 = 0.f;

    const uint32_t brow0 = (uint32_t)((lane & 7) + ((lane >> 4) << 3));
    const uint32_t bc    = (uint32_t)((lane >> 3) & 1);
    const uint32_t vrow0 = (uint32_t)(lane & 15);
    const uint32_t vb    = (uint32_t)(lane >> 4);

    int cs = 0;
    for (int t0 = 0; t0 < ntile; t0++) {
        const int s0 = t0 << 6;
        if (t0 == ntile - 1) { CP_WAIT0(); } else { CP_WAIT1(); }
        __syncthreads();

        if (t0 + 2 < ntile) {
            int ws = cs + 2; if (ws >= 3) ws -= 3;
            const uint32_t st = sb + ws * ASTG + lso;
            const __nv_bfloat16* g = lsrc + lg + (size_t)((t0 + 2) * 64) * KVS;
#pragma unroll
            for (int ci = 0; ci < 16; ci++)
                cpa16(st + swkv((uint32_t)lrow, (uint32_t)ci), g + ci * 8);
            CP_COMMIT();
        }

        const uint32_t sKh = sb + cs * ASTG;
        const uint32_t sKl = sKh + KVT;
        const uint32_t sVh = sKh + 2 * KVT;
        const uint32_t sVl = sKh + 3 * KVT;

        float sacc[8][4];
#pragma unroll
        for (int t = 0; t < 8; t++)
#pragma unroll
            for (int q = 0; q < 4; q++) sacc[t][q] = 0.f;

#pragma unroll
        for (int kk = 0; kk < 8; kk++) {
            const uint32_t kc = bc + kk * 2;
            uint32_t bh[4][4], bl[4][4];
#pragma unroll
            for (int nt = 0; nt < 4; nt++) {
                ldmx4(bh[nt], sKh + swkv(brow0 + nt * 16, kc));
                ldmx4(bl[nt], sKl + swkv(brow0 + nt * 16, kc));
            }
#pragma unroll
            for (int nt = 0; nt < 4; nt++) {
                mma16816(sacc[2 * nt],     qfh[kk], bh[nt][0], bh[nt][1]);
                mma16816(sacc[2 * nt + 1], qfh[kk], bh[nt][2], bh[nt][3]);
            }
#pragma unroll
            for (int nt = 0; nt < 4; nt++) {
                mma16816(sacc[2 * nt],     qfh[kk], bl[nt][0], bl[nt][1]);
                mma16816(sacc[2 * nt + 1], qfh[kk], bl[nt][2], bl[nt][3]);
            }
#pragma unroll
            for (int nt = 0; nt < 4; nt++) {
                mma16816(sacc[2 * nt],     qfl[kk], bh[nt][0], bh[nt][1]);
                mma16816(sacc[2 * nt + 1], qfl[kk], bh[nt][2], bh[nt][3]);
            }
        }

        const int qr0 = q0 + w * 16 + (lane >> 2);
        const int qr1 = qr0 + 8;
        const bool domask = (s0 + 63 > q0 + w * 16);
        float mt0 = -1e30f, mt1 = -1e30f;
#pragma unroll
        for (int t = 0; t < 8; t++) {
            float v0 = sacc[t][0], v1 = sacc[t][1];
            float v2 = sacc[t][2], v3 = sacc[t][3];
            if (domask) {
                int c = s0 + t * 8 + (lane & 3) * 2;
                if (c     > qr0) v0 = -1e30f;
                if (c + 1 > qr0) v1 = -1e30f;
                if (c     > qr1) v2 = -1e30f;
                if (c + 1 > qr1) v3 = -1e30f;
                sacc[t][0] = v0; sacc[t][1] = v1; sacc[t][2] = v2; sacc[t][3] = v3;
            }
            mt0 = fmaxf(mt0, fmaxf(v0, v1));
            mt1 = fmaxf(mt1, fmaxf(v2, v3));
        }
        mt0 = fmaxf(mt0, __shfl_xor_sync(0xffffffffu, mt0, 1));
        mt0 = fmaxf(mt0, __shfl_xor_sync(0xffffffffu, mt0, 2));
        mt1 = fmaxf(mt1, __shfl_xor_sync(0xffffffffu, mt1, 1));
        mt1 = fmaxf(mt1, __shfl_xor_sync(0xffffffffu, mt1, 2));
        float mn0 = fmaxf(m0, mt0), mn1 = fmaxf(m1, mt1);
        float f0 = ex2f(m0 - mn0), f1 = ex2f(m1 - mn1);
        m0 = mn0; m1 = mn1;

        float ls0 = 0.f, ls1 = 0.f;
#pragma unroll
        for (int t = 0; t < 8; t++) {
            sacc[t][0] = ex2f(sacc[t][0] - mn0);
            sacc[t][1] = ex2f(sacc[t][1] - mn0);
            sacc[t][2] = ex2f(sacc[t][2] - mn1);
            sacc[t][3] = ex2f(sacc[t][3] - mn1);
            ls0 += sacc[t][0] + sacc[t][1];
            ls1 += sacc[t][2] + sacc[t][3];
        }
        ls0 += __shfl_xor_sync(0xffffffffu, ls0, 1);
        ls0 += __shfl_xor_sync(0xffffffffu, ls0, 2);
        ls1 += __shfl_xor_sync(0xffffffffu, ls1, 1);
        ls1 += __shfl_xor_sync(0xffffffffu, ls1, 2);
        l0 = l0 * f0 + ls0;
        l1 = l1 * f1 + ls1;
#pragma unroll
        for (int n = 0; n < 16; n++) {
            oacc[n][0] *= f0; oacc[n][1] *= f0;
            oacc[n][2] *= f1; oacc[n][3] *= f1;
        }

#pragma unroll
        for (int ks = 0; ks < 4; ks++) {
            uint32_t pah[4], pal[4];
#pragma unroll
            for (int half = 0; half < 2; half++) {
                float x0 = sacc[2 * ks + half][0], x1 = sacc[2 * ks + half][1];
                float x2 = sacc[2 * ks + half][2], x3 = sacc[2 * ks + half][3];
                uint32_t h01 = packbf(x0, x1);
                uint32_t h23 = packbf(x2, x3);
                pah[2 * half]     = h01;
                pah[2 * half + 1] = h23;
                float h0f = __uint_as_float(h01 << 16);
                float h1f = __uint_as_float(h01 & 0xffff0000u);
                float h2f = __uint_as_float(h23 << 16);
                float h3f = __uint_as_float(h23 & 0xffff0000u);
                pal[2 * half]     = packbf(x0 - h0f, x1 - h1f);
                pal[2 * half + 1] = packbf(x2 - h2f, x3 - h3f);
            }
#pragma unroll
            for (int np = 0; np < 4; np++) {
                const int nt = 2 * np;
                const uint32_t r = vrow0 + ks * 16;
                uint32_t vha[4], vla[4], vhb[4], vlb[4];
                ldmx4t(vha, sVh + swkv(r, vb + nt * 2));
                ldmx4t(vla, sVl + swkv(r, vb + nt * 2));
                ldmx4t(vhb, sVh + swkv(r, vb + (nt + 1) * 2));
                ldmx4t(vlb, sVl + swkv(r, vb + (nt + 1) * 2));
                mma16816(oacc[2 * nt],     pah, vha[0], vha[1]);
                mma16816(oacc[2 * nt + 1], pah, vha[2], vha[3]);
                mma16816(oacc[2 * nt + 2], pah, vhb[0], vhb[1]);
                mma16816(oacc[2 * nt + 3], pah, vhb[2], vhb[3]);
                mma16816(oacc[2 * nt],     pah, vla[0], vla[1]);
                mma16816(oacc[2 * nt + 1], pah, vla[2], vla[3]);
                mma16816(oacc[2 * nt + 2], pah, vlb[0], vlb[1]);
                mma16816(oacc[2 * nt + 3], pah, vlb[2], vlb[3]);
                mma16816(oacc[2 * nt],     pal, vha[0], vha[1]);
                mma16816(oacc[2 * nt + 1], pal, vha[2], vha[3]);
                mma16816(oacc[2 * nt + 2], pal, vhb[0], vhb[1]);
                mma16816(oacc[2 * nt + 3], pal, vhb[2], vhb[3]);
            }
        }
        if (++cs >= 3) cs = 0;
    }

    float il0 = 1.f / l0, il1 = 1.f / l1;
    const int row0 = q0 + w * 16 + (lane >> 2);
#pragma unroll
    for (int n = 0; n < 16; n++) {
        int col = h * HD + n * 8 + (lane & 3) * 2;
        float o0 = oacc[n][0] * il0, o1 = oacc[n][1] * il0;
        float o2 = oacc[n][2] * il1, o3 = oacc[n][3] * il1;
        uint32_t hi01 = packbf(o0, o1);
        uint32_t hi23 = packbf(o2, o3);
        float h0f = __uint_as_float(hi01 << 16);
        float h1f = __uint_as_float(hi01 & 0xffff0000u);
        float h2f = __uint_as_float(hi23 << 16);
        float h3f = __uint_as_float(hi23 & 0xffff0000u);
        uint32_t lo01 = packbf(o0 - h0f, o1 - h1f);
        uint32_t lo23 = packbf(o2 - h2f, o3 - h3f);
        *(uint32_t*)(cxh + (size_t)row0 * QS + col)       = hi01;
        *(uint32_t*)(cxl + (size_t)row0 * QS + col)       = lo01;
        *(uint32_t*)(cxh + (size_t)(row0 + 8) * QS + col) = hi23;
        *(uint32_t*)(cxl + (size_t)(row0 + 8) * QS + col) = lo23;
    }
}

// ============================================================
extern "C" void kernel_launch(void* const* d_in, const int* in_sizes, int n_in,
                              void* d_out, int out_size)
{
    const int*   positions = (const int*)d_in[0];
    const float* hidden    = (const float*)d_in[1];
    const float* qkv_w     = (const float*)d_in[2];
    const float* q_norm_w  = (const float*)d_in[3];
    const float* k_norm_w  = (const float*)d_in[4];
    const float* o_w       = (const float*)d_in[5];
    float* out = (float*)d_out;

    float* qkv;
    cudaGetSymbolAddress((void**)&qkv, g_qkv);
    __nv_bfloat16 *hid_h, *hid_l, *qw_h, *qw_l, *ow_h, *ow_l, *cx_h, *cx_l;
    __nv_bfloat16 *qh, *ql, *kh, *kl, *vh, *vl;
    cudaGetSymbolAddress((void**)&hid_h, g_hid_h);
    cudaGetSymbolAddress((void**)&hid_l, g_hid_l);
    cudaGetSymbolAddress((void**)&qw_h,  g_qkvw_h);
    cudaGetSymbolAddress((void**)&qw_l,  g_qkvw_l);
    cudaGetSymbolAddress((void**)&ow_h,  g_ow_h);
    cudaGetSymbolAddress((void**)&ow_l,  g_ow_l);
    cudaGetSymbolAddress((void**)&cx_h,  g_ctx_h);
    cudaGetSymbolAddress((void**)&cx_l,  g_ctx_l);
    cudaGetSymbolAddress((void**)&qh, g_qh);
    cudaGetSymbolAddress((void**)&ql, g_ql);
    cudaGetSymbolAddress((void**)&kh, g_kh);
    cudaGetSymbolAddress((void**)&kl, g_kl);
    cudaGetSymbolAddress((void**)&vh, g_vh);
    cudaGetSymbolAddress((void**)&vl, g_vl);

    cudaFuncSetAttribute(gemm_mma, cudaFuncAttributeMaxDynamicSharedMemorySize, DSMEM_B);
    cudaFuncSetAttribute(attn_mma, cudaFuncAttributeMaxDynamicSharedMemorySize, ASMEM);

    // 0) fused fp32 -> bf16 hi/lo splits (hidden, qkv_w, o_w in one launch)
    split_all<<<(N4_HID + N4_QW + N4_OW + 255) / 256, 256>>>(
        hidden, qkv_w, o_w, hid_h, hid_l, qw_h, qw_l, ow_h, ow_l);

    // 1) QKV projection (HMMA bf16x3, R8 pipeline)
    gemm_mma<<<dim3(QKVN / 128, TT / 128), 256, DSMEM_B>>>(
        hid_h, hid_l, qw_h, qw_l, qkv, TT, QKVN, HID);

    // 2) fused RMSNorm+RoPE (Q pre-scaled by scale*log2e) + V split
    norm_rope_v<<<dim3(TT, NH + NKV + 2), 128>>>(
        qkv, positions, q_norm_w, k_norm_w, qh, ql, kh, kl, vh, vl);

    // 3) causal GQA flash attention (R10)
    attn_mma<<<dim3(TT / 128, NH), 256, ASMEM>>>(qh, ql, kh, kl, vh, vl, cx_h, cx_l);

    // 4) O projection (HMMA bf16x3, R8 pipeline)
    gemm_mma<<<dim3(HID / 128, TT / 128), 256, DSMEM_B>>>(
        cx_h, cx_l, ow_h, ow_l, out, TT, HID, QS);
}

// round 15
// speedup vs baseline: 1.1264x; 1.1264x over previous
#include <cuda_runtime.h>
#include <cuda_bf16.h>
#include <math.h>
#include <cstdint>

#define TT   2048
#define HID  2048
#define NH   16
#define NKV  8
#define HD   128
#define QS   (NH * HD)          // 2048
#define KVS  (NKV * HD)         // 1024
#define QKVN (QS + 2 * KVS)     // 4096
#define NSM  152

// ---------------- scratch (__device__ globals; allocation-free rule) --------
__device__ float g_qkv[TT * QKVN];            // 32 MB
__device__ __nv_bfloat16 g_hid_h[TT * HID];
__device__ __nv_bfloat16 g_hid_l[TT * HID];
__device__ __nv_bfloat16 g_qkvw_h[QKVN * HID];
__device__ __nv_bfloat16 g_qkvw_l[QKVN * HID];
__device__ __nv_bfloat16 g_ow_h[HID * QS];
__device__ __nv_bfloat16 g_ow_l[HID * QS];
__device__ __nv_bfloat16 g_ctx_h[TT * QS];
__device__ __nv_bfloat16 g_ctx_l[TT * QS];
__device__ __nv_bfloat16 g_qh[TT * QS];
__device__ __nv_bfloat16 g_ql[TT * QS];
__device__ __nv_bfloat16 g_kh[TT * KVS];
__device__ __nv_bfloat16 g_kl[TT * KVS];
__device__ __nv_bfloat16 g_vh[TT * KVS];
__device__ __nv_bfloat16 g_vl[TT * KVS];

// ---------------- helpers -----------------------------------------------------
__device__ __forceinline__ uint32_t smem_u32(const void* p) {
    uint32_t a;
    asm("{ .reg .u64 t; cvta.to.shared.u64 t, %1; cvt.u32.u64 %0, t; }" : "=r"(a) : "l"(p));
    return a;
}

__device__ __forceinline__ void cpa16(uint32_t s, const void* g) {
    asm volatile("cp.async.cg.shared.global [%0], [%1], 16;" :: "r"(s), "l"(g));
}
#define CP_COMMIT() asm volatile("cp.async.commit_group;" ::: "memory")
#define CP_WAIT1()  asm volatile("cp.async.wait_group 1;" ::: "memory")
#define CP_WAIT0()  asm volatile("cp.async.wait_group 0;" ::: "memory")

__device__ __forceinline__ void ldmx4(uint32_t* r, uint32_t addr) {
    asm volatile("ldmatrix.sync.aligned.m8n8.x4.shared.b16 {%0,%1,%2,%3}, [%4];"
                 : "=r"(r[0]), "=r"(r[1]), "=r"(r[2]), "=r"(r[3]) : "r"(addr));
}
__device__ __forceinline__ void ldmx4t(uint32_t* r, uint32_t addr) {
    asm volatile("ldmatrix.sync.aligned.m8n8.x4.trans.shared.b16 {%0,%1,%2,%3}, [%4];"
                 : "=r"(r[0]), "=r"(r[1]), "=r"(r[2]), "=r"(r[3]) : "r"(addr));
}

__device__ __forceinline__ void mma16816(float* d, const uint32_t* a,
                                         uint32_t b0, uint32_t b1) {
    asm volatile(
        "mma.sync.aligned.m16n8k16.row.col.f32.bf16.bf16.f32 "
        "{%0,%1,%2,%3}, {%4,%5,%6,%7}, {%8,%9}, {%0,%1,%2,%3};"
        : "+f"(d[0]), "+f"(d[1]), "+f"(d[2]), "+f"(d[3])
        : "r"(a[0]), "r"(a[1]), "r"(a[2]), "r"(a[3]), "r"(b0), "r"(b1));
}

__device__ __forceinline__ uint32_t packbf(float lo, float hi) {
    uint32_t r;
    asm("cvt.rn.bf16x2.f32 %0, %1, %2;" : "=r"(r) : "f"(hi), "f"(lo));
    return r;
}

__device__ __forceinline__ float ex2f(float x) {
    float y; asm("ex2.approx.f32 %0, %1;" : "=f"(y) : "f"(x)); return y;
}

__device__ __forceinline__ uint32_t sw64(uint32_t row, uint32_t c16) {
    uint32_t line = row >> 1;
    uint32_t slot = (((row & 1) << 2) + c16) ^ (line & 7);
    return (line << 7) + (slot << 4);
}
__device__ __forceinline__ uint32_t swkv(uint32_t row, uint32_t c16) {
    return ((c16 >> 3) << 13) + (row << 7) + (((c16 & 7) ^ (row & 7)) << 4);
}
__device__ __forceinline__ uint32_t swq(uint32_t row, uint32_t c16) {
    return ((c16 >> 3) << 14) + (row << 7) + (((c16 & 7) ^ (row & 7)) << 4);
}

// ---------------- fused fp32 -> bf16 hi/lo split over 3 arrays -----------------
#define N4_HID  (TT * HID / 4)
#define N4_QW   (QKVN * HID / 4)
#define N4_OW   (HID * QS / 4)

__global__ __launch_bounds__(256) void split_all(
    const float* __restrict__ hid, const float* __restrict__ qw,
    const float* __restrict__ ow,
    __nv_bfloat16* __restrict__ hid_h, __nv_bfloat16* __restrict__ hid_l,
    __nv_bfloat16* __restrict__ qw_h,  __nv_bfloat16* __restrict__ qw_l,
    __nv_bfloat16* __restrict__ ow_h,  __nv_bfloat16* __restrict__ ow_l)
{
    int i = blockIdx.x * 256 + threadIdx.x;
    const float* x; __nv_bfloat16* h; __nv_bfloat16* l;
    if (i < N4_HID)              { x = hid; h = hid_h; l = hid_l; }
    else if (i < N4_HID + N4_QW) { i -= N4_HID; x = qw; h = qw_h; l = qw_l; }
    else                         { i -= N4_HID + N4_QW; x = ow; h = ow_h; l = ow_l; }
    float4 v = ((const float4*)x)[i];
    __nv_bfloat16 h0 = __float2bfloat16_rn(v.x);
    __nv_bfloat16 h1 = __float2bfloat16_rn(v.y);
    __nv_bfloat16 h2 = __float2bfloat16_rn(v.z);
    __nv_bfloat16 h3 = __float2bfloat16_rn(v.w);
    __nv_bfloat16 l0 = __float2bfloat16_rn(v.x - __bfloat162float(h0));
    __nv_bfloat16 l1 = __float2bfloat16_rn(v.y - __bfloat162float(h1));
    __nv_bfloat16 l2 = __float2bfloat16_rn(v.z - __bfloat162float(h2));
    __nv_bfloat16 l3 = __float2bfloat16_rn(v.w - __bfloat162float(h3));
    ((ushort4*)h)[i] = make_ushort4(__bfloat16_as_ushort(h0), __bfloat16_as_ushort(h1),
                                    __bfloat16_as_ushort(h2), __bfloat16_as_ushort(h3));
    ((ushort4*)l)[i] = make_ushort4(__bfloat16_as_ushort(l0), __bfloat16_as_ushort(l1),
                                    __bfloat16_as_ushort(l2), __bfloat16_as_ushort(l3));
}

// ---------------- HMMA bf16x3 GEMM (R8 winner, exact) -------------------------
#define TILE_B  8192
#define STAGE_B (4 * TILE_B)
#define DSMEM_B (3 * STAGE_B)

__global__ __launch_bounds__(256, 2) void gemm_mma(
    const __nv_bfloat16* __restrict__ Ah, const __nv_bfloat16* __restrict__ Al,
    const __nv_bfloat16* __restrict__ Bh, const __nv_bfloat16* __restrict__ Bl,
    float* __restrict__ C, int M, int N, int K)
{
    extern __shared__ char sal[];
    const int tid  = threadIdx.x;
    const int wid  = tid >> 5;
    const int lane = tid & 31;
    const int wm   = wid & 3;
    const int wn   = wid >> 2;
    const int bm = blockIdx.y * 128;
    const int bn = blockIdx.x * 128;
    const int NC = K >> 5;

    const uint32_t sb = smem_u32(sal);

    const int r0 = tid >> 2;
    const int c0 = tid & 3;
    const size_t ga = (size_t)(bm + r0) * K + c0 * 8;
    const size_t gb = (size_t)(bn + r0) * K + c0 * 8;
    const uint32_t so_a = sw64((uint32_t)r0, (uint32_t)c0);
    const uint32_t so_b = sw64((uint32_t)(r0 + 64), (uint32_t)c0);

    const uint32_t arow = (uint32_t)(wm * 32 + (lane & 15));
    const uint32_t ac   = (uint32_t)(lane >> 4);
    const uint32_t brow = (uint32_t)(wn * 64 + (lane & 7) + ((lane >> 4) << 3));
    const uint32_t bc   = (uint32_t)((lane >> 3) & 1);

    float acc[2][8][4];
#pragma unroll
    for (int i = 0; i < 2; i++)
#pragma unroll
        for (int j = 0; j < 8; j++)
#pragma unroll
            for (int q = 0; q < 4; q++) acc[i][j][q] = 0.f;

#pragma unroll
    for (int pc = 0; pc < 2; pc++) {
        const size_t kk0 = (size_t)pc << 5;
        const uint32_t st = sb + pc * STAGE_B;
        cpa16(st + 0 * TILE_B + so_a, Ah + ga + kk0);
        cpa16(st + 0 * TILE_B + so_b, Ah + ga + kk0 + 64 * K);
        cpa16(st + 1 * TILE_B + so_a, Al + ga + kk0);
        cpa16(st + 1 * TILE_B + so_b, Al + ga + kk0 + 64 * K);
        cpa16(st + 2 * TILE_B + so_a, Bh + gb + kk0);
        cpa16(st + 2 * TILE_B + so_b, Bh + gb + kk0 + 64 * K);
        cpa16(st + 3 * TILE_B + so_a, Bl + gb + kk0);
        cpa16(st + 3 * TILE_B + so_b, Bl + gb + kk0 + 64 * K);
        CP_COMMIT();
    }

    int cs = 0;
    for (int c = 0; c < NC; c++) {
        if (c == NC - 1) { CP_WAIT0(); } else { CP_WAIT1(); }
        __syncthreads();

        if (c + 2 < NC) {
            int ws = cs + 2; if (ws >= 3) ws -= 3;
            const size_t kk0 = (size_t)(c + 2) << 5;
            const uint32_t st = sb + ws * STAGE_B;
            cpa16(st + 0 * TILE_B + so_a, Ah + ga + kk0);
            cpa16(st + 0 * TILE_B + so_b, Ah + ga + kk0 + 64 * K);
            cpa16(st + 1 * TILE_B + so_a, Al + ga + kk0);
            cpa16(st + 1 * TILE_B + so_b, Al + ga + kk0 + 64 * K);
            cpa16(st + 2 * TILE_B + so_a, Bh + gb + kk0);
            cpa16(st + 2 * TILE_B + so_b, Bh + gb + kk0 + 64 * K);
            cpa16(st + 3 * TILE_B + so_a, Bl + gb + kk0);
            cpa16(st + 3 * TILE_B + so_b, Bl + gb + kk0 + 64 * K);
            CP_COMMIT();
        }

        const uint32_t sAh = sb + cs * STAGE_B;
        const uint32_t sAl = sAh + TILE_B;
        const uint32_t sBh = sAh + 2 * TILE_B;
        const uint32_t sBl = sAh + 3 * TILE_B;

#pragma unroll
        for (int kk = 0; kk < 2; kk++) {
            const uint32_t ac16 = ac + kk * 2;
            const uint32_t bc16 = bc + kk * 2;
            uint32_t ah[2][4], al[2][4];
            ldmx4(ah[0], sAh + sw64(arow,      ac16));
            ldmx4(ah[1], sAh + sw64(arow + 16, ac16));
            ldmx4(al[0], sAl + sw64(arow,      ac16));
            ldmx4(al[1], sAl + sw64(arow + 16, ac16));
#pragma unroll
            for (int np = 0; np < 2; np++) {
                const int nt0 = 2 * np, nt1 = 2 * np + 1;
                uint32_t b0h[4], b1h[4], b0l[4], b1l[4];
                ldmx4(b0h, sBh + sw64(brow + nt0 * 16, bc16));
                ldmx4(b1h, sBh + sw64(brow + nt1 * 16, bc16));
                ldmx4(b0l, sBl + sw64(brow + nt0 * 16, bc16));
                ldmx4(b1l, sBl + sw64(brow + nt1 * 16, bc16));
                mma16816(acc[0][2 * nt0],     ah[0], b0h[0], b0h[1]);
                mma16816(acc[0][2 * nt0 + 1], ah[0], b0h[2], b0h[3]);
                mma16816(acc[1][2 * nt0],     ah[1], b0h[0], b0h[1]);
                mma16816(acc[1][2 * nt0 + 1], ah[1], b0h[2], b0h[3]);
                mma16816(acc[0][2 * nt1],     ah[0], b1h[0], b1h[1]);
                mma16816(acc[0][2 * nt1 + 1], ah[0], b1h[2], b1h[3]);
                mma16816(acc[1][2 * nt1],     ah[1], b1h[0], b1h[1]);
                mma16816(acc[1][2 * nt1 + 1], ah[1], b1h[2], b1h[3]);
                mma16816(acc[0][2 * nt0],     ah[0], b0l[0], b0l[1]);
                mma16816(acc[0][2 * nt0 + 1], ah[0], b0l[2], b0l[3]);
                mma16816(acc[1][2 * nt0],     ah[1], b0l[0], b0l[1]);
                mma16816(acc[1][2 * nt0 + 1], ah[1], b0l[2], b0l[3]);
                mma16816(acc[0][2 * nt1],     ah[0], b1l[0], b1l[1]);
                mma16816(acc[0][2 * nt1 + 1], ah[0], b1l[2], b1l[3]);
                mma16816(acc[1][2 * nt1],     ah[1], b1l[0], b1l[1]);
                mma16816(acc[1][2 * nt1 + 1], ah[1], b1l[2], b1l[3]);
                mma16816(acc[0][2 * nt0],     al[0], b0h[0], b0h[1]);
                mma16816(acc[0][2 * nt0 + 1], al[0], b0h[2], b0h[3]);
                mma16816(acc[1][2 * nt0],     al[1], b0h[0], b0h[1]);
                mma16816(acc[1][2 * nt0 + 1], al[1], b0h[2], b0h[3]);
                mma16816(acc[0][2 * nt1],     al[0], b1h[0], b1h[1]);
                mma16816(acc[0][2 * nt1 + 1], al[0], b1h[2], b1h[3]);
                mma16816(acc[1][2 * nt1],     al[1], b1h[0], b1h[1]);
                mma16816(acc[1][2 * nt1 + 1], al[1], b1h[2], b1h[3]);
            }
        }
        if (++cs >= 3) cs = 0;
    }

    const int mr = bm + wm * 32 + (lane >> 2);
    const int nc0 = bn + wn * 64 + (lane & 3) * 2;
#pragma unroll
    for (int mt = 0; mt < 2; mt++) {
#pragma unroll
        for (int n8 = 0; n8 < 8; n8++) {
            int row = mr + mt * 16;
            int col = nc0 + n8 * 8;
            *(float2*)(C + (size_t)row * N + col) =
                make_float2(acc[mt][n8][0], acc[mt][n8][1]);
            *(float2*)(C + (size_t)(row + 8) * N + col) =
                make_float2(acc[mt][n8][2], acc[mt][n8][3]);
        }
    }
}

// ---------------- fused RMSNorm+RoPE (Q/K) and V split ------------------------
__global__ __launch_bounds__(128) void norm_rope_v(
    const float* __restrict__ qkv, const int* __restrict__ pos,
    const float* __restrict__ qw,  const float* __restrict__ kw,
    __nv_bfloat16* __restrict__ qh, __nv_bfloat16* __restrict__ ql,
    __nv_bfloat16* __restrict__ kh, __nv_bfloat16* __restrict__ kl,
    __nv_bfloat16* __restrict__ vh, __nv_bfloat16* __restrict__ vl)
{
    const int t  = blockIdx.x;
    const int hh = blockIdx.y;
    const int d  = threadIdx.x;

    if (hh >= NH + NKV) {
        int i = ((hh - NH - NKV) * 128 + d) * 4;
        float4 v = *(const float4*)(qkv + (size_t)t * QKVN + QS + KVS + i);
        __nv_bfloat16 h0 = __float2bfloat16_rn(v.x);
        __nv_bfloat16 h1 = __float2bfloat16_rn(v.y);
        __nv_bfloat16 h2 = __float2bfloat16_rn(v.z);
        __nv_bfloat16 h3 = __float2bfloat16_rn(v.w);
        __nv_bfloat16 l0 = __float2bfloat16_rn(v.x - __bfloat162float(h0));
        __nv_bfloat16 l1 = __float2bfloat16_rn(v.y - __bfloat162float(h1));
        __nv_bfloat16 l2 = __float2bfloat16_rn(v.z - __bfloat162float(h2));
        __nv_bfloat16 l3 = __float2bfloat16_rn(v.w - __bfloat162float(h3));
        size_t o = (size_t)t * KVS + i;
        *(ushort4*)(vh + o) = make_ushort4(__bfloat16_as_ushort(h0), __bfloat16_as_ushort(h1),
                                           __bfloat16_as_ushort(h2), __bfloat16_as_ushort(h3));
        *(ushort4*)(vl + o) = make_ushort4(__bfloat16_as_ushort(l0), __bfloat16_as_ushort(l1),
                                           __bfloat16_as_ushort(l2), __bfloat16_as_ushort(l3));
        return;
    }

    const float* src; const float* w;
    __nv_bfloat16* dsth; __nv_bfloat16* dstl; size_t dofs;
    bool isq = (hh < NH);
    if (isq) {
        src = qkv + (size_t)t * QKVN + hh * HD;
        w = qw;
        dsth = qh; dstl = ql;
        dofs = ((size_t)t * NH + hh) * HD + d;
    } else {
        int khd = hh - NH;
        src = qkv + (size_t)t * QKVN + QS + khd * HD;
        w = kw;
        dsth = kh; dstl = kl;
        dofs = ((size_t)t * NKV + khd) * HD + d;
    }

    float x = src[d];
    float ss = x * x;
#pragma unroll
    for (int o = 16; o > 0; o >>= 1)
        ss += __shfl_xor_sync(0xffffffffu, ss, o);

    __shared__ float red[4];
    __shared__ float xs[128];
    if ((d & 31) == 0) red[d >> 5] = ss;
    __syncthreads();
    float ms = (red[0] + red[1] + red[2] + red[3]) * (1.f / 128.f);
    float xn = x * rsqrtf(ms + 1e-6f) * w[d];
    xs[d] = xn;
    __syncthreads();

    float p = (float)pos[t];
    int i = d & 63;
    float freq = p * exp2f((float)i * -0.2076205059304601f);
    float s, c;
    sincosf(freq, &s, &c);
    float other = (d < 64) ? xs[d + 64] : xs[d - 64];
    float val = (d < 64) ? (xn * c - other * s) : (xn * c + other * s);

    if (isq) val *= (0.088388347648318447f * 1.4426950408889634f);  // scale*log2e

    __nv_bfloat16 hv = __float2bfloat16_rn(val);
    dsth[dofs] = hv;
    dstl[dofs] = __float2bfloat16_rn(val - __bfloat162float(hv));
}

// ---------------- HMMA flash attention: static LPT schedule, grid=152 ---------
#define KVT    16384
#define ASTG   (4 * KVT)
#define AQOFF  (2 * ASTG)
#define ASMEM  (3 * ASTG)
#define NITEMS 256               // 16 heads x 16 q-blocks

__global__ __launch_bounds__(256, 1) void attn_mma(
    const __nv_bfloat16* __restrict__ Qh, const __nv_bfloat16* __restrict__ Ql,
    const __nv_bfloat16* __restrict__ Kh, const __nv_bfloat16* __restrict__ Kl,
    const __nv_bfloat16* __restrict__ Vh, const __nv_bfloat16* __restrict__ Vl,
    __nv_bfloat16* __restrict__ cxh, __nv_bfloat16* __restrict__ cxl)
{
    extern __shared__ char sm[];
    const int tid = threadIdx.x;
    const int w   = tid >> 5;
    const int lane = tid & 31;
    const uint32_t sb = smem_u32(sm);
    const int cta = blockIdx.x;
    const int nit = (NITEMS - 1 - cta >= NSM) ? 2 : 1;

    const uint32_t brow0 = (uint32_t)((lane & 7) + ((lane >> 4) << 3));
    const uint32_t bcc   = (uint32_t)((lane >> 3) & 1);
    const uint32_t vrow0 = (uint32_t)(lane & 15);
    const uint32_t vb    = (uint32_t)(lane >> 4);

    for (int it = 0; it < nit; it++) {
        if (it) __syncthreads();   // previous item fully done with smem

        const int item = (it == 0) ? cta : (NITEMS - 1 - cta);
        const int qblk = 15 - (item >> 4);    // descending work order
        const int h    = item & 15;
        const int kvh  = h >> 1;
        const int q0   = qblk * 128;
        const int ntile = (q0 >> 6) + 2;

        const int sub  = tid >> 6;
        const int lrow = tid & 63;
        const __nv_bfloat16* lsrc = (sub == 0) ? Kh : (sub == 1) ? Kl
                                  : (sub == 2) ? Vh : Vl;
        const uint32_t lso = (uint32_t)(sub * KVT);
        const size_t lg = (size_t)lrow * KVS + kvh * HD;

#pragma unroll
        for (int p = 0; p < 2; p++) {
            const uint32_t st = sb + p * ASTG + lso;
            const __nv_bfloat16* g = lsrc + lg + (size_t)(p * 64) * KVS;
#pragma unroll
            for (int ci = 0; ci < 16; ci++)
                cpa16(st + swkv((uint32_t)lrow, (uint32_t)ci), g + ci * 8);
            CP_COMMIT();
        }

        {
            const int part = tid >> 7, row = tid & 127;
            const __nv_bfloat16* src = (part ? Ql : Qh) + (size_t)(q0 + row) * QS + h * HD;
            char* d = sm + AQOFF + part * 32768;
#pragma unroll
            for (int ci = 0; ci < 16; ci++)
                *(uint4*)(d + swq((uint32_t)row, (uint32_t)ci)) = *(const uint4*)(src + ci * 8);
        }
        __syncthreads();

        uint32_t qfh[8][4], qfl[8][4];
        {
            const uint32_t arow = (uint32_t)(w * 16 + (lane & 15));
#pragma unroll
            for (int kk = 0; kk < 8; kk++) {
                uint32_t c16 = (uint32_t)(lane >> 4) + kk * 2;
                ldmx4(qfh[kk], sb + AQOFF + swq(arow, c16));
                ldmx4(qfl[kk], sb + AQOFF + 32768 + swq(arow, c16));
            }
        }

        float oacc[16][4];
#pragma unroll
        for (int n = 0; n < 16; n++)
#pragma unroll
            for (int q = 0; q < 4; q++) oacc[n][q] = 0.f;
        float m0 = -1e30f, m1 = -1e30f, l0 = 0.f, l1 = 0.f;

        int cs = 0;
        for (int t0 = 0; t0 < ntile; t0++) {
            const int s0 = t0 << 6;
            if (t0 == ntile - 1) { CP_WAIT0(); } else { CP_WAIT1(); }
            __syncthreads();

            if (t0 + 2 < ntile) {
                int ws = cs + 2; if (ws >= 3) ws -= 3;
                const uint32_t st = sb + ws * ASTG + lso;
                const __nv_bfloat16* g = lsrc + lg + (size_t)((t0 + 2) * 64) * KVS;
#pragma unroll
                for (int ci = 0; ci < 16; ci++)
                    cpa16(st + swkv((uint32_t)lrow, (uint32_t)ci), g + ci * 8);
                CP_COMMIT();
            }

            const uint32_t sKh = sb + cs * ASTG;
            const uint32_t sKl = sKh + KVT;
            const uint32_t sVh = sKh + 2 * KVT;
            const uint32_t sVl = sKh + 3 * KVT;

            float sacc[8][4];
#pragma unroll
            for (int t = 0; t < 8; t++)
#pragma unroll
                for (int q = 0; q < 4; q++) sacc[t][q] = 0.f;

#pragma unroll
            for (int kk = 0; kk < 8; kk++) {
                const uint32_t kc = bcc + kk * 2;
                uint32_t bh[4][4], bl[4][4];
#pragma unroll
                for (int nt = 0; nt < 4; nt++) {
                    ldmx4(bh[nt], sKh + swkv(brow0 + nt * 16, kc));
                    ldmx4(bl[nt], sKl + swkv(brow0 + nt * 16, kc));
                }
#pragma unroll
                for (int nt = 0; nt < 4; nt++) {
                    mma16816(sacc[2 * nt],     qfh[kk], bh[nt][0], bh[nt][1]);
                    mma16816(sacc[2 * nt + 1], qfh[kk], bh[nt][2], bh[nt][3]);
                }
#pragma unroll
                for (int nt = 0; nt < 4; nt++) {
                    mma16816(sacc[2 * nt],     qfh[kk], bl[nt][0], bl[nt][1]);
                    mma16816(sacc[2 * nt + 1], qfh[kk], bl[nt][2], bl[nt][3]);
                }
#pragma unroll
                for (int nt = 0; nt < 4; nt++) {
                    mma16816(sacc[2 * nt],     qfl[kk], bh[nt][0], bh[nt][1]);
                    mma16816(sacc[2 * nt + 1], qfl[kk], bh[nt][2], bh[nt][3]);
                }
            }

            const int qr0 = q0 + w * 16 + (lane >> 2);
            const int qr1 = qr0 + 8;
            const bool domask = (s0 + 63 > q0 + w * 16);
            float mt0 = -1e30f, mt1 = -1e30f;
#pragma unroll
            for (int t = 0; t < 8; t++) {
                float v0 = sacc[t][0], v1 = sacc[t][1];
                float v2 = sacc[t][2], v3 = sacc[t][3];
                if (domask) {
                    int c = s0 + t * 8 + (lane & 3) * 2;
                    if (c     > qr0) v0 = -1e30f;
                    if (c + 1 > qr0) v1 = -1e30f;
                    if (c     > qr1) v2 = -1e30f;
                    if (c + 1 > qr1) v3 = -1e30f;
                    sacc[t][0] = v0; sacc[t][1] = v1; sacc[t][2] = v2; sacc[t][3] = v3;
                }
                mt0 = fmaxf(mt0, fmaxf(v0, v1));
                mt1 = fmaxf(mt1, fmaxf(v2, v3));
            }
            mt0 = fmaxf(mt0, __shfl_xor_sync(0xffffffffu, mt0, 1));
            mt0 = fmaxf(mt0, __shfl_xor_sync(0xffffffffu, mt0, 2));
            mt1 = fmaxf(mt1, __shfl_xor_sync(0xffffffffu, mt1, 1));
            mt1 = fmaxf(mt1, __shfl_xor_sync(0xffffffffu, mt1, 2));
            float mn0 = fmaxf(m0, mt0), mn1 = fmaxf(m1, mt1);
            float f0 = ex2f(m0 - mn0), f1 = ex2f(m1 - mn1);
            m0 = mn0; m1 = mn1;

            float ls0 = 0.f, ls1 = 0.f;
#pragma unroll
            for (int t = 0; t < 8; t++) {
                sacc[t][0] = ex2f(sacc[t][0] - mn0);
                sacc[t][1] = ex2f(sacc[t][1] - mn0);
                sacc[t][2] = ex2f(sacc[t][2] - mn1);
                sacc[t][3] = ex2f(sacc[t][3] - mn1);
                ls0 += sacc[t][0] + sacc[t][1];
                ls1 += sacc[t][2] + sacc[t][3];
            }
            ls0 += __shfl_xor_sync(0xffffffffu, ls0, 1);
            ls0 += __shfl_xor_sync(0xffffffffu, ls0, 2);
            ls1 += __shfl_xor_sync(0xffffffffu, ls1, 1);
            ls1 += __shfl_xor_sync(0xffffffffu, ls1, 2);
            l0 = l0 * f0 + ls0;
            l1 = l1 * f1 + ls1;
#pragma unroll
            for (int n = 0; n < 16; n++) {
                oacc[n][0] *= f0; oacc[n][1] *= f0;
                oacc[n][2] *= f1; oacc[n][3] *= f1;
            }

#pragma unroll
            for (int ks = 0; ks < 4; ks++) {
                uint32_t pah[4], pal[4];
#pragma unroll
                for (int half = 0; half < 2; half++) {
                    float x0 = sacc[2 * ks + half][0], x1 = sacc[2 * ks + half][1];
                    float x2 = sacc[2 * ks + half][2], x3 = sacc[2 * ks + half][3];
                    uint32_t h01 = packbf(x0, x1);
                    uint32_t h23 = packbf(x2, x3);
                    pah[2 * half]     = h01;
                    pah[2 * half + 1] = h23;
                    float h0f = __uint_as_float(h01 << 16);
                    float h1f = __uint_as_float(h01 & 0xffff0000u);
                    float h2f = __uint_as_float(h23 << 16);
                    float h3f = __uint_as_float(h23 & 0xffff0000u);
                    pal[2 * half]     = packbf(x0 - h0f, x1 - h1f);
                    pal[2 * half + 1] = packbf(x2 - h2f, x3 - h3f);
                }
#pragma unroll
                for (int np = 0; np < 4; np++) {
                    const int nt = 2 * np;
                    const uint32_t r = vrow0 + ks * 16;
                    uint32_t vha[4], vla[4], vhb[4], vlb[4];
                    ldmx4t(vha, sVh + swkv(r, vb + nt * 2));
                    ldmx4t(vla, sVl + swkv(r, vb + nt * 2));
                    ldmx4t(vhb, sVh + swkv(r, vb + (nt + 1) * 2));
                    ldmx4t(vlb, sVl + swkv(r, vb + (nt + 1) * 2));
                    mma16816(oacc[2 * nt],     pah, vha[0], vha[1]);
                    mma16816(oacc[2 * nt + 1], pah, vha[2], vha[3]);
                    mma16816(oacc[2 * nt + 2], pah, vhb[0], vhb[1]);
                    mma16816(oacc[2 * nt + 3], pah, vhb[2], vhb[3]);
                    mma16816(oacc[2 * nt],     pah, vla[0], vla[1]);
                    mma16816(oacc[2 * nt + 1], pah, vla[2], vla[3]);
                    mma16816(oacc[2 * nt + 2], pah, vlb[0], vlb[1]);
                    mma16816(oacc[2 * nt + 3], pah, vlb[2], vlb[3]);
                    mma16816(oacc[2 * nt],     pal, vha[0], vha[1]);
                    mma16816(oacc[2 * nt + 1], pal, vha[2], vha[3]);
                    mma16816(oacc[2 * nt + 2], pal, vhb[0], vhb[1]);
                    mma16816(oacc[2 * nt + 3], pal, vhb[2], vhb[3]);
                }
            }
            if (++cs >= 3) cs = 0;
        }

        float il0 = 1.f / l0, il1 = 1.f / l1;
        const int row0 = q0 + w * 16 + (lane >> 2);
#pragma unroll
        for (int n = 0; n < 16; n++) {
            int col = h * HD + n * 8 + (lane & 3) * 2;
            float o0 = oacc[n][0] * il0, o1 = oacc[n][1] * il0;
            float o2 = oacc[n][2] * il1, o3 = oacc[n][3] * il1;
            uint32_t hi01 = packbf(o0, o1);
            uint32_t hi23 = packbf(o2, o3);
            float h0f = __uint_as_float(hi01 << 16);
            float h1f = __uint_as_float(hi01 & 0xffff0000u);
            float h2f = __uint_as_float(hi23 << 16);
            float h3f = __uint_as_float(hi23 & 0xffff0000u);
            uint32_t lo01 = packbf(o0 - h0f, o1 - h1f);
            uint32_t lo23 = packbf(o2 - h2f, o3 - h3f);
            *(uint32_t*)(cxh + (size_t)row0 * QS + col)       = hi01;
            *(uint32_t*)(cxl + (size_t)row0 * QS + col)       = lo01;
            *(uint32_t*)(cxh + (size_t)(row0 + 8) * QS + col) = hi23;
            *(uint32_t*)(cxl + (size_t)(row0 + 8) * QS + col) = lo23;
        }
    }
}

// ============================================================
extern "C" void kernel_launch(void* const* d_in, const int* in_sizes, int n_in,
                              void* d_out, int out_size)
{
    const int*   positions = (const int*)d_in[0];
    const float* hidden    = (const float*)d_in[1];
    const float* qkv_w     = (const float*)d_in[2];
    const float* q_norm_w  = (const float*)d_in[3];
    const float* k_norm_w  = (const float*)d_in[4];
    const float* o_w       = (const float*)d_in[5];
    float* out = (float*)d_out;

    float* qkv;
    cudaGetSymbolAddress((void**)&qkv, g_qkv);
    __nv_bfloat16 *hid_h, *hid_l, *qw_h, *qw_l, *ow_h, *ow_l, *cx_h, *cx_l;
    __nv_bfloat16 *qh, *ql, *kh, *kl, *vh, *vl;
    cudaGetSymbolAddress((void**)&hid_h, g_hid_h);
    cudaGetSymbolAddress((void**)&hid_l, g_hid_l);
    cudaGetSymbolAddress((void**)&qw_h,  g_qkvw_h);
    cudaGetSymbolAddress((void**)&qw_l,  g_qkvw_l);
    cudaGetSymbolAddress((void**)&ow_h,  g_ow_h);
    cudaGetSymbolAddress((void**)&ow_l,  g_ow_l);
    cudaGetSymbolAddress((void**)&cx_h,  g_ctx_h);
    cudaGetSymbolAddress((void**)&cx_l,  g_ctx_l);
    cudaGetSymbolAddress((void**)&qh, g_qh);
    cudaGetSymbolAddress((void**)&ql, g_ql);
    cudaGetSymbolAddress((void**)&kh, g_kh);
    cudaGetSymbolAddress((void**)&kl, g_kl);
    cudaGetSymbolAddress((void**)&vh, g_vh);
    cudaGetSymbolAddress((void**)&vl, g_vl);

    cudaFuncSetAttribute(gemm_mma, cudaFuncAttributeMaxDynamicSharedMemorySize, DSMEM_B);
    cudaFuncSetAttribute(attn_mma, cudaFuncAttributeMaxDynamicSharedMemorySize, ASMEM);

    // 0) fused fp32 -> bf16 hi/lo splits
    split_all<<<(N4_HID + N4_QW + N4_OW + 255) / 256, 256>>>(
        hidden, qkv_w, o_w, hid_h, hid_l, qw_h, qw_l, ow_h, ow_l);

    // 1) QKV projection
    gemm_mma<<<dim3(QKVN / 128, TT / 128), 256, DSMEM_B>>>(
        hid_h, hid_l, qw_h, qw_l, qkv, TT, QKVN, HID);

    // 2) fused RMSNorm+RoPE (Q pre-scaled by scale*log2e) + V split
    norm_rope_v<<<dim3(TT, NH + NKV + 2), 128>>>(
        qkv, positions, q_norm_w, k_norm_w, qh, ql, kh, kl, vh, vl);

    // 3) causal GQA flash attention (static LPT schedule, single wave)
    attn_mma<<<NSM, 256, ASMEM>>>(qh, ql, kh, kl, vh, vl, cx_h, cx_l);

    // 4) O projection
    gemm_mma<<<dim3(HID / 128, TT / 128), 256, DSMEM_B>>>(
        cx_h, cx_l, ow_h, ow_l, out, TT, HID, QS);
}

// round 16
// speedup vs baseline: 1.1599x; 1.0298x over previous
#include <cuda_runtime.h>
#include <cuda_bf16.h>
#include <math.h>
#include <cstdint>

#define TT   2048
#define HID  2048
#define NH   16
#define NKV  8
#define HD   128
#define QS   (NH * HD)          // 2048
#define KVS  (NKV * HD)         // 1024
#define QKVN (QS + 2 * KVS)     // 4096
#define NSM  152

// ---------------- scratch (__device__ globals; allocation-free rule) --------
__device__ float g_qkv[TT * QKVN];            // 32 MB
__device__ __nv_bfloat16 g_hid_h[TT * HID];
__device__ __nv_bfloat16 g_hid_l[TT * HID];
__device__ __nv_bfloat16 g_qkvw_h[QKVN * HID];
__device__ __nv_bfloat16 g_qkvw_l[QKVN * HID];
__device__ __nv_bfloat16 g_ow_h[HID * QS];
__device__ __nv_bfloat16 g_ow_l[HID * QS];
__device__ __nv_bfloat16 g_ctx_h[TT * QS];
__device__ __nv_bfloat16 g_ctx_l[TT * QS];
__device__ __nv_bfloat16 g_qh[TT * QS];
__device__ __nv_bfloat16 g_ql[TT * QS];
__device__ __nv_bfloat16 g_kh[TT * KVS];
__device__ __nv_bfloat16 g_kl[TT * KVS];
__device__ __nv_bfloat16 g_vh[TT * KVS];
__device__ __nv_bfloat16 g_vl[TT * KVS];

// ---------------- helpers -----------------------------------------------------
__device__ __forceinline__ uint32_t smem_u32(const void* p) {
    uint32_t a;
    asm("{ .reg .u64 t; cvta.to.shared.u64 t, %1; cvt.u32.u64 %0, t; }" : "=r"(a) : "l"(p));
    return a;
}

__device__ __forceinline__ void cpa16(uint32_t s, const void* g) {
    asm volatile("cp.async.cg.shared.global [%0], [%1], 16;" :: "r"(s), "l"(g));
}
#define CP_COMMIT() asm volatile("cp.async.commit_group;" ::: "memory")
#define CP_WAIT1()  asm volatile("cp.async.wait_group 1;" ::: "memory")
#define CP_WAIT0()  asm volatile("cp.async.wait_group 0;" ::: "memory")

__device__ __forceinline__ void ldmx4(uint32_t* r, uint32_t addr) {
    asm volatile("ldmatrix.sync.aligned.m8n8.x4.shared.b16 {%0,%1,%2,%3}, [%4];"
                 : "=r"(r[0]), "=r"(r[1]), "=r"(r[2]), "=r"(r[3]) : "r"(addr));
}
__device__ __forceinline__ void ldmx4t(uint32_t* r, uint32_t addr) {
    asm volatile("ldmatrix.sync.aligned.m8n8.x4.trans.shared.b16 {%0,%1,%2,%3}, [%4];"
                 : "=r"(r[0]), "=r"(r[1]), "=r"(r[2]), "=r"(r[3]) : "r"(addr));
}

__device__ __forceinline__ void mma16816(float* d, const uint32_t* a,
                                         uint32_t b0, uint32_t b1) {
    asm volatile(
        "mma.sync.aligned.m16n8k16.row.col.f32.bf16.bf16.f32 "
        "{%0,%1,%2,%3}, {%4,%5,%6,%7}, {%8,%9}, {%0,%1,%2,%3};"
        : "+f"(d[0]), "+f"(d[1]), "+f"(d[2]), "+f"(d[3])
        : "r"(a[0]), "r"(a[1]), "r"(a[2]), "r"(a[3]), "r"(b0), "r"(b1));
}

__device__ __forceinline__ uint32_t packbf(float lo, float hi) {
    uint32_t r;
    asm("cvt.rn.bf16x2.f32 %0, %1, %2;" : "=r"(r) : "f"(hi), "f"(lo));
    return r;
}

__device__ __forceinline__ float ex2f(float x) {
    float y; asm("ex2.approx.f32 %0, %1;" : "=f"(y) : "f"(x)); return y;
}

__device__ __forceinline__ uint32_t sw64(uint32_t row, uint32_t c16) {
    uint32_t line = row >> 1;
    uint32_t slot = (((row & 1) << 2) + c16) ^ (line & 7);
    return (line << 7) + (slot << 4);
}
__device__ __forceinline__ uint32_t swkv(uint32_t row, uint32_t c16) {
    return ((c16 >> 3) << 13) + (row << 7) + (((c16 & 7) ^ (row & 7)) << 4);
}
__device__ __forceinline__ uint32_t swq(uint32_t row, uint32_t c16) {
    return ((c16 >> 3) << 14) + (row << 7) + (((c16 & 7) ^ (row & 7)) << 4);
}

// ---------------- fused fp32 -> bf16 hi/lo split over 3 arrays -----------------
#define N4_HID  (TT * HID / 4)
#define N4_QW   (QKVN * HID / 4)
#define N4_OW   (HID * QS / 4)

__global__ __launch_bounds__(256) void split_all(
    const float* __restrict__ hid, const float* __restrict__ qw,
    const float* __restrict__ ow,
    __nv_bfloat16* __restrict__ hid_h, __nv_bfloat16* __restrict__ hid_l,
    __nv_bfloat16* __restrict__ qw_h,  __nv_bfloat16* __restrict__ qw_l,
    __nv_bfloat16* __restrict__ ow_h,  __nv_bfloat16* __restrict__ ow_l)
{
    int i = blockIdx.x * 256 + threadIdx.x;
    const float* x; __nv_bfloat16* h; __nv_bfloat16* l;
    if (i < N4_HID)              { x = hid; h = hid_h; l = hid_l; }
    else if (i < N4_HID + N4_QW) { i -= N4_HID; x = qw; h = qw_h; l = qw_l; }
    else                         { i -= N4_HID + N4_QW; x = ow; h = ow_h; l = ow_l; }
    float4 v = ((const float4*)x)[i];
    __nv_bfloat16 h0 = __float2bfloat16_rn(v.x);
    __nv_bfloat16 h1 = __float2bfloat16_rn(v.y);
    __nv_bfloat16 h2 = __float2bfloat16_rn(v.z);
    __nv_bfloat16 h3 = __float2bfloat16_rn(v.w);
    __nv_bfloat16 l0 = __float2bfloat16_rn(v.x - __bfloat162float(h0));
    __nv_bfloat16 l1 = __float2bfloat16_rn(v.y - __bfloat162float(h1));
    __nv_bfloat16 l2 = __float2bfloat16_rn(v.z - __bfloat162float(h2));
    __nv_bfloat16 l3 = __float2bfloat16_rn(v.w - __bfloat162float(h3));
    ((ushort4*)h)[i] = make_ushort4(__bfloat16_as_ushort(h0), __bfloat16_as_ushort(h1),
                                    __bfloat16_as_ushort(h2), __bfloat16_as_ushort(h3));
    ((ushort4*)l)[i] = make_ushort4(__bfloat16_as_ushort(l0), __bfloat16_as_ushort(l1),
                                    __bfloat16_as_ushort(l2), __bfloat16_as_ushort(l3));
}

// ---------------- HMMA bf16x3 GEMM (R8 winner, exact) -------------------------
#define TILE_B  8192
#define STAGE_B (4 * TILE_B)
#define DSMEM_B (3 * STAGE_B)

__global__ __launch_bounds__(256, 2) void gemm_mma(
    const __nv_bfloat16* __restrict__ Ah, const __nv_bfloat16* __restrict__ Al,
    const __nv_bfloat16* __restrict__ Bh, const __nv_bfloat16* __restrict__ Bl,
    float* __restrict__ C, int M, int N, int K)
{
    extern __shared__ char sal[];
    const int tid  = threadIdx.x;
    const int wid  = tid >> 5;
    const int lane = tid & 31;
    const int wm   = wid & 3;
    const int wn   = wid >> 2;
    const int bm = blockIdx.y * 128;
    const int bn = blockIdx.x * 128;
    const int NC = K >> 5;

    const uint32_t sb = smem_u32(sal);

    const int r0 = tid >> 2;
    const int c0 = tid & 3;
    const size_t ga = (size_t)(bm + r0) * K + c0 * 8;
    const size_t gb = (size_t)(bn + r0) * K + c0 * 8;
    const uint32_t so_a = sw64((uint32_t)r0, (uint32_t)c0);
    const uint32_t so_b = sw64((uint32_t)(r0 + 64), (uint32_t)c0);

    const uint32_t arow = (uint32_t)(wm * 32 + (lane & 15));
    const uint32_t ac   = (uint32_t)(lane >> 4);
    const uint32_t brow = (uint32_t)(wn * 64 + (lane & 7) + ((lane >> 4) << 3));
    const uint32_t bc   = (uint32_t)((lane >> 3) & 1);

    float acc[2][8][4];
#pragma unroll
    for (int i = 0; i < 2; i++)
#pragma unroll
        for (int j = 0; j < 8; j++)
#pragma unroll
            for (int q = 0; q < 4; q++) acc[i][j][q] = 0.f;

#pragma unroll
    for (int pc = 0; pc < 2; pc++) {
        const size_t kk0 = (size_t)pc << 5;
        const uint32_t st = sb + pc * STAGE_B;
        cpa16(st + 0 * TILE_B + so_a, Ah + ga + kk0);
        cpa16(st + 0 * TILE_B + so_b, Ah + ga + kk0 + 64 * K);
        cpa16(st + 1 * TILE_B + so_a, Al + ga + kk0);
        cpa16(st + 1 * TILE_B + so_b, Al + ga + kk0 + 64 * K);
        cpa16(st + 2 * TILE_B + so_a, Bh + gb + kk0);
        cpa16(st + 2 * TILE_B + so_b, Bh + gb + kk0 + 64 * K);
        cpa16(st + 3 * TILE_B + so_a, Bl + gb + kk0);
        cpa16(st + 3 * TILE_B + so_b, Bl + gb + kk0 + 64 * K);
        CP_COMMIT();
    }

    int cs = 0;
    for (int c = 0; c < NC; c++) {
        if (c == NC - 1) { CP_WAIT0(); } else { CP_WAIT1(); }
        __syncthreads();

        if (c + 2 < NC) {
            int ws = cs + 2; if (ws >= 3) ws -= 3;
            const size_t kk0 = (size_t)(c + 2) << 5;
            const uint32_t st = sb + ws * STAGE_B;
            cpa16(st + 0 * TILE_B + so_a, Ah + ga + kk0);
            cpa16(st + 0 * TILE_B + so_b, Ah + ga + kk0 + 64 * K);
            cpa16(st + 1 * TILE_B + so_a, Al + ga + kk0);
            cpa16(st + 1 * TILE_B + so_b, Al + ga + kk0 + 64 * K);
            cpa16(st + 2 * TILE_B + so_a, Bh + gb + kk0);
            cpa16(st + 2 * TILE_B + so_b, Bh + gb + kk0 + 64 * K);
            cpa16(st + 3 * TILE_B + so_a, Bl + gb + kk0);
            cpa16(st + 3 * TILE_B + so_b, Bl + gb + kk0 + 64 * K);
            CP_COMMIT();
        }

        const uint32_t sAh = sb + cs * STAGE_B;
        const uint32_t sAl = sAh + TILE_B;
        const uint32_t sBh = sAh + 2 * TILE_B;
        const uint32_t sBl = sAh + 3 * TILE_B;

#pragma unroll
        for (int kk = 0; kk < 2; kk++) {
            const uint32_t ac16 = ac + kk * 2;
            const uint32_t bc16 = bc + kk * 2;
            uint32_t ah[2][4], al[2][4];
            ldmx4(ah[0], sAh + sw64(arow,      ac16));
            ldmx4(ah[1], sAh + sw64(arow + 16, ac16));
            ldmx4(al[0], sAl + sw64(arow,      ac16));
            ldmx4(al[1], sAl + sw64(arow + 16, ac16));
#pragma unroll
            for (int np = 0; np < 2; np++) {
                const int nt0 = 2 * np, nt1 = 2 * np + 1;
                uint32_t b0h[4], b1h[4], b0l[4], b1l[4];
                ldmx4(b0h, sBh + sw64(brow + nt0 * 16, bc16));
                ldmx4(b1h, sBh + sw64(brow + nt1 * 16, bc16));
                ldmx4(b0l, sBl + sw64(brow + nt0 * 16, bc16));
                ldmx4(b1l, sBl + sw64(brow + nt1 * 16, bc16));
                mma16816(acc[0][2 * nt0],     ah[0], b0h[0], b0h[1]);
                mma16816(acc[0][2 * nt0 + 1], ah[0], b0h[2], b0h[3]);
                mma16816(acc[1][2 * nt0],     ah[1], b0h[0], b0h[1]);
                mma16816(acc[1][2 * nt0 + 1], ah[1], b0h[2], b0h[3]);
                mma16816(acc[0][2 * nt1],     ah[0], b1h[0], b1h[1]);
                mma16816(acc[0][2 * nt1 + 1], ah[0], b1h[2], b1h[3]);
                mma16816(acc[1][2 * nt1],     ah[1], b1h[0], b1h[1]);
                mma16816(acc[1][2 * nt1 + 1], ah[1], b1h[2], b1h[3]);
                mma16816(acc[0][2 * nt0],     ah[0], b0l[0], b0l[1]);
                mma16816(acc[0][2 * nt0 + 1], ah[0], b0l[2], b0l[3]);
                mma16816(acc[1][2 * nt0],     ah[1], b0l[0], b0l[1]);
                mma16816(acc[1][2 * nt0 + 1], ah[1], b0l[2], b0l[3]);
                mma16816(acc[0][2 * nt1],     ah[0], b1l[0], b1l[1]);
                mma16816(acc[0][2 * nt1 + 1], ah[0], b1l[2], b1l[3]);
                mma16816(acc[1][2 * nt1],     ah[1], b1l[0], b1l[1]);
                mma16816(acc[1][2 * nt1 + 1], ah[1], b1l[2], b1l[3]);
                mma16816(acc[0][2 * nt0],     al[0], b0h[0], b0h[1]);
                mma16816(acc[0][2 * nt0 + 1], al[0], b0h[2], b0h[3]);
                mma16816(acc[1][2 * nt0],     al[1], b0h[0], b0h[1]);
                mma16816(acc[1][2 * nt0 + 1], al[1], b0h[2], b0h[3]);
                mma16816(acc[0][2 * nt1],     al[0], b1h[0], b1h[1]);
                mma16816(acc[0][2 * nt1 + 1], al[0], b1h[2], b1h[3]);
                mma16816(acc[1][2 * nt1],     al[1], b1h[0], b1h[1]);
                mma16816(acc[1][2 * nt1 + 1], al[1], b1h[2], b1h[3]);
            }
        }
        if (++cs >= 3) cs = 0;
    }

    const int mr = bm + wm * 32 + (lane >> 2);
    const int nc0 = bn + wn * 64 + (lane & 3) * 2;
#pragma unroll
    for (int mt = 0; mt < 2; mt++) {
#pragma unroll
        for (int n8 = 0; n8 < 8; n8++) {
            int row = mr + mt * 16;
            int col = nc0 + n8 * 8;
            *(float2*)(C + (size_t)row * N + col) =
                make_float2(acc[mt][n8][0], acc[mt][n8][1]);
            *(float2*)(C + (size_t)(row + 8) * N + col) =
                make_float2(acc[mt][n8][2], acc[mt][n8][3]);
        }
    }
}

// ---------------- fused RMSNorm+RoPE (Q/K) and V split ------------------------
__global__ __launch_bounds__(128) void norm_rope_v(
    const float* __restrict__ qkv, const int* __restrict__ pos,
    const float* __restrict__ qw,  const float* __restrict__ kw,
    __nv_bfloat16* __restrict__ qh, __nv_bfloat16* __restrict__ ql,
    __nv_bfloat16* __restrict__ kh, __nv_bfloat16* __restrict__ kl,
    __nv_bfloat16* __restrict__ vh, __nv_bfloat16* __restrict__ vl)
{
    const int t  = blockIdx.x;
    const int hh = blockIdx.y;
    const int d  = threadIdx.x;

    if (hh >= NH + NKV) {
        int i = ((hh - NH - NKV) * 128 + d) * 4;
        float4 v = *(const float4*)(qkv + (size_t)t * QKVN + QS + KVS + i);
        __nv_bfloat16 h0 = __float2bfloat16_rn(v.x);
        __nv_bfloat16 h1 = __float2bfloat16_rn(v.y);
        __nv_bfloat16 h2 = __float2bfloat16_rn(v.z);
        __nv_bfloat16 h3 = __float2bfloat16_rn(v.w);
        __nv_bfloat16 l0 = __float2bfloat16_rn(v.x - __bfloat162float(h0));
        __nv_bfloat16 l1 = __float2bfloat16_rn(v.y - __bfloat162float(h1));
        __nv_bfloat16 l2 = __float2bfloat16_rn(v.z - __bfloat162float(h2));
        __nv_bfloat16 l3 = __float2bfloat16_rn(v.w - __bfloat162float(h3));
        size_t o = (size_t)t * KVS + i;
        *(ushort4*)(vh + o) = make_ushort4(__bfloat16_as_ushort(h0), __bfloat16_as_ushort(h1),
                                           __bfloat16_as_ushort(h2), __bfloat16_as_ushort(h3));
        *(ushort4*)(vl + o) = make_ushort4(__bfloat16_as_ushort(l0), __bfloat16_as_ushort(l1),
                                           __bfloat16_as_ushort(l2), __bfloat16_as_ushort(l3));
        return;
    }

    const float* src; const float* w;
    __nv_bfloat16* dsth; __nv_bfloat16* dstl; size_t dofs;
    bool isq = (hh < NH);
    if (isq) {
        src = qkv + (size_t)t * QKVN + hh * HD;
        w = qw;
        dsth = qh; dstl = ql;
        dofs = ((size_t)t * NH + hh) * HD + d;
    } else {
        int khd = hh - NH;
        src = qkv + (size_t)t * QKVN + QS + khd * HD;
        w = kw;
        dsth = kh; dstl = kl;
        dofs = ((size_t)t * NKV + khd) * HD + d;
    }

    float x = src[d];
    float ss = x * x;
#pragma unroll
    for (int o = 16; o > 0; o >>= 1)
        ss += __shfl_xor_sync(0xffffffffu, ss, o);

    __shared__ float red[4];
    __shared__ float xs[128];
    if ((d & 31) == 0) red[d >> 5] = ss;
    __syncthreads();
    float ms = (red[0] + red[1] + red[2] + red[3]) * (1.f / 128.f);
    float xn = x * rsqrtf(ms + 1e-6f) * w[d];
    xs[d] = xn;
    __syncthreads();

    float p = (float)pos[t];
    int i = d & 63;
    float freq = p * exp2f((float)i * -0.2076205059304601f);
    float s, c;
    sincosf(freq, &s, &c);
    float other = (d < 64) ? xs[d + 64] : xs[d - 64];
    float val = (d < 64) ? (xn * c - other * s) : (xn * c + other * s);

    if (isq) val *= (0.088388347648318447f * 1.4426950408889634f);  // scale*log2e

    __nv_bfloat16 hv = __float2bfloat16_rn(val);
    dsth[dofs] = hv;
    dstl[dofs] = __float2bfloat16_rn(val - __bfloat162float(hv));
}

// ---------------- HMMA flash attention: optimal LPT schedule, grid=152 --------
// Items sorted descending by ntile (size = 32 - 2*(item>>4)).
// CTAs 0..47: single heavy item (sizes 32,30,28) -> load 28..32.
// CTAs 48..151: pair (c, 303-c); every pair sums to exactly 28 tiles.
// Critical path = 32 tiles (vs 34 with plain snake; ideal 28.6).
#define KVT    16384
#define ASTG   (4 * KVT)
#define AQOFF  (2 * ASTG)
#define ASMEM  (3 * ASTG)
#define NITEMS 256               // 16 heads x 16 q-blocks

__global__ __launch_bounds__(256, 1) void attn_mma(
    const __nv_bfloat16* __restrict__ Qh, const __nv_bfloat16* __restrict__ Ql,
    const __nv_bfloat16* __restrict__ Kh, const __nv_bfloat16* __restrict__ Kl,
    const __nv_bfloat16* __restrict__ Vh, const __nv_bfloat16* __restrict__ Vl,
    __nv_bfloat16* __restrict__ cxh, __nv_bfloat16* __restrict__ cxl)
{
    extern __shared__ char sm[];
    const int tid = threadIdx.x;
    const int w   = tid >> 5;
    const int lane = tid & 31;
    const uint32_t sb = smem_u32(sm);
    const int cta = blockIdx.x;
    const int nit = (cta < 48) ? 1 : 2;

    const uint32_t brow0 = (uint32_t)((lane & 7) + ((lane >> 4) << 3));
    const uint32_t bcc   = (uint32_t)((lane >> 3) & 1);
    const uint32_t vrow0 = (uint32_t)(lane & 15);
    const uint32_t vb    = (uint32_t)(lane >> 4);

    for (int it = 0; it < nit; it++) {
        if (it) __syncthreads();   // previous item fully done with smem

        const int item = (it == 0) ? cta : (303 - cta);
        const int qblk = 15 - (item >> 4);    // descending work order
        const int h    = item & 15;
        const int kvh  = h >> 1;
        const int q0   = qblk * 128;
        const int ntile = (q0 >> 6) + 2;

        const int sub  = tid >> 6;
        const int lrow = tid & 63;
        const __nv_bfloat16* lsrc = (sub == 0) ? Kh : (sub == 1) ? Kl
                                  : (sub == 2) ? Vh : Vl;
        const uint32_t lso = (uint32_t)(sub * KVT);
        const size_t lg = (size_t)lrow * KVS + kvh * HD;

#pragma unroll
        for (int p = 0; p < 2; p++) {
            const uint32_t st = sb + p * ASTG + lso;
            const __nv_bfloat16* g = lsrc + lg + (size_t)(p * 64) * KVS;
#pragma unroll
            for (int ci = 0; ci < 16; ci++)
                cpa16(st + swkv((uint32_t)lrow, (uint32_t)ci), g + ci * 8);
            CP_COMMIT();
        }

        {
            const int part = tid >> 7, row = tid & 127;
            const __nv_bfloat16* src = (part ? Ql : Qh) + (size_t)(q0 + row) * QS + h * HD;
            char* d = sm + AQOFF + part * 32768;
#pragma unroll
            for (int ci = 0; ci < 16; ci++)
                *(uint4*)(d + swq((uint32_t)row, (uint32_t)ci)) = *(const uint4*)(src + ci * 8);
        }
        __syncthreads();

        uint32_t qfh[8][4], qfl[8][4];
        {
            const uint32_t arow = (uint32_t)(w * 16 + (lane & 15));
#pragma unroll
            for (int kk = 0; kk < 8; kk++) {
                uint32_t c16 = (uint32_t)(lane >> 4) + kk * 2;
                ldmx4(qfh[kk], sb + AQOFF + swq(arow, c16));
                ldmx4(qfl[kk], sb + AQOFF + 32768 + swq(arow, c16));
            }
        }

        float oacc[16][4];
#pragma unroll
        for (int n = 0; n < 16; n++)
#pragma unroll
            for (int q = 0; q < 4; q++) oacc[n][q] = 0.f;
        float m0 = -1e30f, m1 = -1e30f, l0 = 0.f, l1 = 0.f;

        int cs = 0;
        for (int t0 = 0; t0 < ntile; t0++) {
            const int s0 = t0 << 6;
            if (t0 == ntile - 1) { CP_WAIT0(); } else { CP_WAIT1(); }
            __syncthreads();

            if (t0 + 2 < ntile) {
                int ws = cs + 2; if (ws >= 3) ws -= 3;
                const uint32_t st = sb + ws * ASTG + lso;
                const __nv_bfloat16* g = lsrc + lg + (size_t)((t0 + 2) * 64) * KVS;
#pragma unroll
                for (int ci = 0; ci < 16; ci++)
                    cpa16(st + swkv((uint32_t)lrow, (uint32_t)ci), g + ci * 8);
                CP_COMMIT();
            }

            const uint32_t sKh = sb + cs * ASTG;
            const uint32_t sKl = sKh + KVT;
            const uint32_t sVh = sKh + 2 * KVT;
            const uint32_t sVl = sKh + 3 * KVT;

            float sacc[8][4];
#pragma unroll
            for (int t = 0; t < 8; t++)
#pragma unroll
                for (int q = 0; q < 4; q++) sacc[t][q] = 0.f;

#pragma unroll
            for (int kk = 0; kk < 8; kk++) {
                const uint32_t kc = bcc + kk * 2;
                uint32_t bh[4][4], bl[4][4];
#pragma unroll
                for (int nt = 0; nt < 4; nt++) {
                    ldmx4(bh[nt], sKh + swkv(brow0 + nt * 16, kc));
                    ldmx4(bl[nt], sKl + swkv(brow0 + nt * 16, kc));
                }
#pragma unroll
                for (int nt = 0; nt < 4; nt++) {
                    mma16816(sacc[2 * nt],     qfh[kk], bh[nt][0], bh[nt][1]);
                    mma16816(sacc[2 * nt + 1], qfh[kk], bh[nt][2], bh[nt][3]);
                }
#pragma unroll
                for (int nt = 0; nt < 4; nt++) {
                    mma16816(sacc[2 * nt],     qfh[kk], bl[nt][0], bl[nt][1]);
                    mma16816(sacc[2 * nt + 1], qfh[kk], bl[nt][2], bl[nt][3]);
                }
#pragma unroll
                for (int nt = 0; nt < 4; nt++) {
                    mma16816(sacc[2 * nt],     qfl[kk], bh[nt][0], bh[nt][1]);
                    mma16816(sacc[2 * nt + 1], qfl[kk], bh[nt][2], bh[nt][3]);
                }
            }

            const int qr0 = q0 + w * 16 + (lane >> 2);
            const int qr1 = qr0 + 8;
            const bool domask = (s0 + 63 > q0 + w * 16);
            float mt0 = -1e30f, mt1 = -1e30f;
#pragma unroll
            for (int t = 0; t < 8; t++) {
                float v0 = sacc[t][0], v1 = sacc[t][1];
                float v2 = sacc[t][2], v3 = sacc[t][3];
                if (domask) {
                    int c = s0 + t * 8 + (lane & 3) * 2;
                    if (c     > qr0) v0 = -1e30f;
                    if (c + 1 > qr0) v1 = -1e30f;
                    if (c     > qr1) v2 = -1e30f;
                    if (c + 1 > qr1) v3 = -1e30f;
                    sacc[t][0] = v0; sacc[t][1] = v1; sacc[t][2] = v2; sacc[t][3] = v3;
                }
                mt0 = fmaxf(mt0, fmaxf(v0, v1));
                mt1 = fmaxf(mt1, fmaxf(v2, v3));
            }
            mt0 = fmaxf(mt0, __shfl_xor_sync(0xffffffffu, mt0, 1));
            mt0 = fmaxf(mt0, __shfl_xor_sync(0xffffffffu, mt0, 2));
            mt1 = fmaxf(mt1, __shfl_xor_sync(0xffffffffu, mt1, 1));
            mt1 = fmaxf(mt1, __shfl_xor_sync(0xffffffffu, mt1, 2));
            float mn0 = fmaxf(m0, mt0), mn1 = fmaxf(m1, mt1);
            float f0 = ex2f(m0 - mn0), f1 = ex2f(m1 - mn1);
            m0 = mn0; m1 = mn1;

            float ls0 = 0.f, ls1 = 0.f;
#pragma unroll
            for (int t = 0; t < 8; t++) {
                sacc[t][0] = ex2f(sacc[t][0] - mn0);
                sacc[t][1] = ex2f(sacc[t][1] - mn0);
                sacc[t][2] = ex2f(sacc[t][2] - mn1);
                sacc[t][3] = ex2f(sacc[t][3] - mn1);
                ls0 += sacc[t][0] + sacc[t][1];
                ls1 += sacc[t][2] + sacc[t][3];
            }
            ls0 += __shfl_xor_sync(0xffffffffu, ls0, 1);
            ls0 += __shfl_xor_sync(0xffffffffu, ls0, 2);
            ls1 += __shfl_xor_sync(0xffffffffu, ls1, 1);
            ls1 += __shfl_xor_sync(0xffffffffu, ls1, 2);
            l0 = l0 * f0 + ls0;
            l1 = l1 * f1 + ls1;
#pragma unroll
            for (int n = 0; n < 16; n++) {
                oacc[n][0] *= f0; oacc[n][1] *= f0;
                oacc[n][2] *= f1; oacc[n][3] *= f1;
            }

#pragma unroll
            for (int ks = 0; ks < 4; ks++) {
                uint32_t pah[4], pal[4];
#pragma unroll
                for (int half = 0; half < 2; half++) {
                    float x0 = sacc[2 * ks + half][0], x1 = sacc[2 * ks + half][1];
                    float x2 = sacc[2 * ks + half][2], x3 = sacc[2 * ks + half][3];
                    uint32_t h01 = packbf(x0, x1);
                    uint32_t h23 = packbf(x2, x3);
                    pah[2 * half]     = h01;
                    pah[2 * half + 1] = h23;
                    float h0f = __uint_as_float(h01 << 16);
                    float h1f = __uint_as_float(h01 & 0xffff0000u);
                    float h2f = __uint_as_float(h23 << 16);
                    float h3f = __uint_as_float(h23 & 0xffff0000u);
                    pal[2 * half]     = packbf(x0 - h0f, x1 - h1f);
                    pal[2 * half + 1] = packbf(x2 - h2f, x3 - h3f);
                }
#pragma unroll
                for (int np = 0; np < 4; np++) {
                    const int nt = 2 * np;
                    const uint32_t r = vrow0 + ks * 16;
                    uint32_t vha[4], vla[4], vhb[4], vlb[4];
                    ldmx4t(vha, sVh + swkv(r, vb + nt * 2));
                    ldmx4t(vla, sVl + swkv(r, vb + nt * 2));
                    ldmx4t(vhb, sVh + swkv(r, vb + (nt + 1) * 2));
                    ldmx4t(vlb, sVl + swkv(r, vb + (nt + 1) * 2));
                    mma16816(oacc[2 * nt],     pah, vha[0], vha[1]);
                    mma16816(oacc[2 * nt + 1], pah, vha[2], vha[3]);
                    mma16816(oacc[2 * nt + 2], pah, vhb[0], vhb[1]);
                    mma16816(oacc[2 * nt + 3], pah, vhb[2], vhb[3]);
                    mma16816(oacc[2 * nt],     pah, vla[0], vla[1]);
                    mma16816(oacc[2 * nt + 1], pah, vla[2], vla[3]);
                    mma16816(oacc[2 * nt + 2], pah, vlb[0], vlb[1]);
                    mma16816(oacc[2 * nt + 3], pah, vlb[2], vlb[3]);
                    mma16816(oacc[2 * nt],     pal, vha[0], vha[1]);
                    mma16816(oacc[2 * nt + 1], pal, vha[2], vha[3]);
                    mma16816(oacc[2 * nt + 2], pal, vhb[0], vhb[1]);
                    mma16816(oacc[2 * nt + 3], pal, vhb[2], vhb[3]);
                }
            }
            if (++cs >= 3) cs = 0;
        }

        float il0 = 1.f / l0, il1 = 1.f / l1;
        const int row0 = q0 + w * 16 + (lane >> 2);
#pragma unroll
        for (int n = 0; n < 16; n++) {
            int col = h * HD + n * 8 + (lane & 3) * 2;
            float o0 = oacc[n][0] * il0, o1 = oacc[n][1] * il0;
            float o2 = oacc[n][2] * il1, o3 = oacc[n][3] * il1;
            uint32_t hi01 = packbf(o0, o1);
            uint32_t hi23 = packbf(o2, o3);
            float h0f = __uint_as_float(hi01 << 16);
            float h1f = __uint_as_float(hi01 & 0xffff0000u);
            float h2f = __uint_as_float(hi23 << 16);
            float h3f = __uint_as_float(hi23 & 0xffff0000u);
            uint32_t lo01 = packbf(o0 - h0f, o1 - h1f);
            uint32_t lo23 = packbf(o2 - h2f, o3 - h3f);
            *(uint32_t*)(cxh + (size_t)row0 * QS + col)       = hi01;
            *(uint32_t*)(cxl + (size_t)row0 * QS + col)       = lo01;
            *(uint32_t*)(cxh + (size_t)(row0 + 8) * QS + col) = hi23;
            *(uint32_t*)(cxl + (size_t)(row0 + 8) * QS + col) = lo23;
        }
    }
}

// ============================================================
extern "C" void kernel_launch(void* const* d_in, const int* in_sizes, int n_in,
                              void* d_out, int out_size)
{
    const int*   positions = (const int*)d_in[0];
    const float* hidden    = (const float*)d_in[1];
    const float* qkv_w     = (const float*)d_in[2];
    const float* q_norm_w  = (const float*)d_in[3];
    const float* k_norm_w  = (const float*)d_in[4];
    const float* o_w       = (const float*)d_in[5];
    float* out = (float*)d_out;

    float* qkv;
    cudaGetSymbolAddress((void**)&qkv, g_qkv);
    __nv_bfloat16 *hid_h, *hid_l, *qw_h, *qw_l, *ow_h, *ow_l, *cx_h, *cx_l;
    __nv_bfloat16 *qh, *ql, *kh, *kl, *vh, *vl;
    cudaGetSymbolAddress((void**)&hid_h, g_hid_h);
    cudaGetSymbolAddress((void**)&hid_l, g_hid_l);
    cudaGetSymbolAddress((void**)&qw_h,  g_qkvw_h);
    cudaGetSymbolAddress((void**)&qw_l,  g_qkvw_l);
    cudaGetSymbolAddress((void**)&ow_h,  g_ow_h);
    cudaGetSymbolAddress((void**)&ow_l,  g_ow_l);
    cudaGetSymbolAddress((void**)&cx_h,  g_ctx_h);
    cudaGetSymbolAddress((void**)&cx_l,  g_ctx_l);
    cudaGetSymbolAddress((void**)&qh, g_qh);
    cudaGetSymbolAddress((void**)&ql, g_ql);
    cudaGetSymbolAddress((void**)&kh, g_kh);
    cudaGetSymbolAddress((void**)&kl, g_kl);
    cudaGetSymbolAddress((void**)&vh, g_vh);
    cudaGetSymbolAddress((void**)&vl, g_vl);

    cudaFuncSetAttribute(gemm_mma, cudaFuncAttributeMaxDynamicSharedMemorySize, DSMEM_B);
    cudaFuncSetAttribute(attn_mma, cudaFuncAttributeMaxDynamicSharedMemorySize, ASMEM);

    // 0) fused fp32 -> bf16 hi/lo splits
    split_all<<<(N4_HID + N4_QW + N4_OW + 255) / 256, 256>>>(
        hidden, qkv_w, o_w, hid_h, hid_l, qw_h, qw_l, ow_h, ow_l);

    // 1) QKV projection
    gemm_mma<<<dim3(QKVN / 128, TT / 128), 256, DSMEM_B>>>(
        hid_h, hid_l, qw_h, qw_l, qkv, TT, QKVN, HID);

    // 2) fused RMSNorm+RoPE (Q pre-scaled by scale*log2e) + V split
    norm_rope_v<<<dim3(TT, NH + NKV + 2), 128>>>(
        qkv, positions, q_norm_w, k_norm_w, qh, ql, kh, kl, vh, vl);

    // 3) causal GQA flash attention (optimal LPT: 48 singles + 104 exact-28 pairs)
    attn_mma<<<NSM, 256, ASMEM>>>(qh, ql, kh, kl, vh, vl, cx_h, cx_l);

    // 4) O projection
    gemm_mma<<<dim3(HID / 128, TT / 128), 256, DSMEM_B>>>(
        cx_h, cx_l, ow_h, ow_l, out, TT, HID, QS);
}

// round 17
// speedup vs baseline: 1.1778x; 1.0155x over previous
#include <cuda_runtime.h>
#include <cuda_bf16.h>
#include <math.h>
#include <cstdint>

#define TT   2048
#define HID  2048
#define NH   16
#define NKV  8
#define HD   128
#define QS   (NH * HD)          // 2048
#define KVS  (NKV * HD)         // 1024
#define QKVN (QS + 2 * KVS)     // 4096
#define NSM  152

// ---------------- scratch (__device__ globals; allocation-free rule) --------
__device__ float g_qkv[TT * QKVN];            // 32 MB
__device__ __nv_bfloat16 g_hid_h[TT * HID];
__device__ __nv_bfloat16 g_hid_l[TT * HID];
__device__ __nv_bfloat16 g_qkvw_h[QKVN * HID];
__device__ __nv_bfloat16 g_qkvw_l[QKVN * HID];
__device__ __nv_bfloat16 g_ow_h[HID * QS];
__device__ __nv_bfloat16 g_ow_l[HID * QS];
__device__ __nv_bfloat16 g_ctx_h[TT * QS];
__device__ __nv_bfloat16 g_ctx_l[TT * QS];
__device__ __nv_bfloat16 g_qh[TT * QS];
__device__ __nv_bfloat16 g_ql[TT * QS];
__device__ __nv_bfloat16 g_kh[TT * KVS];
__device__ __nv_bfloat16 g_kl[TT * KVS];
__device__ __nv_bfloat16 g_vh[TT * KVS];
__device__ __nv_bfloat16 g_vl[TT * KVS];

// ---------------- helpers -----------------------------------------------------
__device__ __forceinline__ uint32_t smem_u32(const void* p) {
    uint32_t a;
    asm("{ .reg .u64 t; cvta.to.shared.u64 t, %1; cvt.u32.u64 %0, t; }" : "=r"(a) : "l"(p));
    return a;
}

__device__ __forceinline__ void cpa16(uint32_t s, const void* g) {
    asm volatile("cp.async.cg.shared.global [%0], [%1], 16;" :: "r"(s), "l"(g));
}
#define CP_COMMIT() asm volatile("cp.async.commit_group;" ::: "memory")
#define CP_WAIT1()  asm volatile("cp.async.wait_group 1;" ::: "memory")
#define CP_WAIT0()  asm volatile("cp.async.wait_group 0;" ::: "memory")

__device__ __forceinline__ void ldmx4(uint32_t* r, uint32_t addr) {
    asm volatile("ldmatrix.sync.aligned.m8n8.x4.shared.b16 {%0,%1,%2,%3}, [%4];"
                 : "=r"(r[0]), "=r"(r[1]), "=r"(r[2]), "=r"(r[3]) : "r"(addr));
}
__device__ __forceinline__ void ldmx4t(uint32_t* r, uint32_t addr) {
    asm volatile("ldmatrix.sync.aligned.m8n8.x4.trans.shared.b16 {%0,%1,%2,%3}, [%4];"
                 : "=r"(r[0]), "=r"(r[1]), "=r"(r[2]), "=r"(r[3]) : "r"(addr));
}

__device__ __forceinline__ void mma16816(float* d, const uint32_t* a,
                                         uint32_t b0, uint32_t b1) {
    asm volatile(
        "mma.sync.aligned.m16n8k16.row.col.f32.bf16.bf16.f32 "
        "{%0,%1,%2,%3}, {%4,%5,%6,%7}, {%8,%9}, {%0,%1,%2,%3};"
        : "+f"(d[0]), "+f"(d[1]), "+f"(d[2]), "+f"(d[3])
        : "r"(a[0]), "r"(a[1]), "r"(a[2]), "r"(a[3]), "r"(b0), "r"(b1));
}

__device__ __forceinline__ uint32_t packbf(float lo, float hi) {
    uint32_t r;
    asm("cvt.rn.bf16x2.f32 %0, %1, %2;" : "=r"(r) : "f"(hi), "f"(lo));
    return r;
}

__device__ __forceinline__ float ex2f(float x) {
    float y; asm("ex2.approx.f32 %0, %1;" : "=f"(y) : "f"(x)); return y;
}

__device__ __forceinline__ uint32_t sw64(uint32_t row, uint32_t c16) {
    uint32_t line = row >> 1;
    uint32_t slot = (((row & 1) << 2) + c16) ^ (line & 7);
    return (line << 7) + (slot << 4);
}
__device__ __forceinline__ uint32_t swkv(uint32_t row, uint32_t c16) {
    return ((c16 >> 3) << 13) + (row << 7) + (((c16 & 7) ^ (row & 7)) << 4);
}
__device__ __forceinline__ uint32_t swq(uint32_t row, uint32_t c16) {
    return ((c16 >> 3) << 14) + (row << 7) + (((c16 & 7) ^ (row & 7)) << 4);
}

// ---------------- fused fp32 -> bf16 hi/lo split over 3 arrays -----------------
#define N4_HID  (TT * HID / 4)
#define N4_QW   (QKVN * HID / 4)
#define N4_OW   (HID * QS / 4)

__global__ __launch_bounds__(256) void split_all(
    const float* __restrict__ hid, const float* __restrict__ qw,
    const float* __restrict__ ow,
    __nv_bfloat16* __restrict__ hid_h, __nv_bfloat16* __restrict__ hid_l,
    __nv_bfloat16* __restrict__ qw_h,  __nv_bfloat16* __restrict__ qw_l,
    __nv_bfloat16* __restrict__ ow_h,  __nv_bfloat16* __restrict__ ow_l)
{
    int i = blockIdx.x * 256 + threadIdx.x;
    const float* x; __nv_bfloat16* h; __nv_bfloat16* l;
    if (i < N4_HID)              { x = hid; h = hid_h; l = hid_l; }
    else if (i < N4_HID + N4_QW) { i -= N4_HID; x = qw; h = qw_h; l = qw_l; }
    else                         { i -= N4_HID + N4_QW; x = ow; h = ow_h; l = ow_l; }
    float4 v = ((const float4*)x)[i];
    __nv_bfloat16 h0 = __float2bfloat16_rn(v.x);
    __nv_bfloat16 h1 = __float2bfloat16_rn(v.y);
    __nv_bfloat16 h2 = __float2bfloat16_rn(v.z);
    __nv_bfloat16 h3 = __float2bfloat16_rn(v.w);
    __nv_bfloat16 l0 = __float2bfloat16_rn(v.x - __bfloat162float(h0));
    __nv_bfloat16 l1 = __float2bfloat16_rn(v.y - __bfloat162float(h1));
    __nv_bfloat16 l2 = __float2bfloat16_rn(v.z - __bfloat162float(h2));
    __nv_bfloat16 l3 = __float2bfloat16_rn(v.w - __bfloat162float(h3));
    ((ushort4*)h)[i] = make_ushort4(__bfloat16_as_ushort(h0), __bfloat16_as_ushort(h1),
                                    __bfloat16_as_ushort(h2), __bfloat16_as_ushort(h3));
    ((ushort4*)l)[i] = make_ushort4(__bfloat16_as_ushort(l0), __bfloat16_as_ushort(l1),
                                    __bfloat16_as_ushort(l2), __bfloat16_as_ushort(l3));
}

// ---------------- HMMA bf16x3 GEMM (R8 winner, exact) -------------------------
#define TILE_B  8192
#define STAGE_B (4 * TILE_B)
#define DSMEM_B (3 * STAGE_B)

__global__ __launch_bounds__(256, 2) void gemm_mma(
    const __nv_bfloat16* __restrict__ Ah, const __nv_bfloat16* __restrict__ Al,
    const __nv_bfloat16* __restrict__ Bh, const __nv_bfloat16* __restrict__ Bl,
    float* __restrict__ C, int M, int N, int K)
{
    extern __shared__ char sal[];
    const int tid  = threadIdx.x;
    const int wid  = tid >> 5;
    const int lane = tid & 31;
    const int wm   = wid & 3;
    const int wn   = wid >> 2;
    const int bm = blockIdx.y * 128;
    const int bn = blockIdx.x * 128;
    const int NC = K >> 5;

    const uint32_t sb = smem_u32(sal);

    const int r0 = tid >> 2;
    const int c0 = tid & 3;
    const size_t ga = (size_t)(bm + r0) * K + c0 * 8;
    const size_t gb = (size_t)(bn + r0) * K + c0 * 8;
    const uint32_t so_a = sw64((uint32_t)r0, (uint32_t)c0);
    const uint32_t so_b = sw64((uint32_t)(r0 + 64), (uint32_t)c0);

    const uint32_t arow = (uint32_t)(wm * 32 + (lane & 15));
    const uint32_t ac   = (uint32_t)(lane >> 4);
    const uint32_t brow = (uint32_t)(wn * 64 + (lane & 7) + ((lane >> 4) << 3));
    const uint32_t bc   = (uint32_t)((lane >> 3) & 1);

    float acc[2][8][4];
#pragma unroll
    for (int i = 0; i < 2; i++)
#pragma unroll
        for (int j = 0; j < 8; j++)
#pragma unroll
            for (int q = 0; q < 4; q++) acc[i][j][q] = 0.f;

#pragma unroll
    for (int pc = 0; pc < 2; pc++) {
        const size_t kk0 = (size_t)pc << 5;
        const uint32_t st = sb + pc * STAGE_B;
        cpa16(st + 0 * TILE_B + so_a, Ah + ga + kk0);
        cpa16(st + 0 * TILE_B + so_b, Ah + ga + kk0 + 64 * K);
        cpa16(st + 1 * TILE_B + so_a, Al + ga + kk0);
        cpa16(st + 1 * TILE_B + so_b, Al + ga + kk0 + 64 * K);
        cpa16(st + 2 * TILE_B + so_a, Bh + gb + kk0);
        cpa16(st + 2 * TILE_B + so_b, Bh + gb + kk0 + 64 * K);
        cpa16(st + 3 * TILE_B + so_a, Bl + gb + kk0);
        cpa16(st + 3 * TILE_B + so_b, Bl + gb + kk0 + 64 * K);
        CP_COMMIT();
    }

    int cs = 0;
    for (int c = 0; c < NC; c++) {
        if (c == NC - 1) { CP_WAIT0(); } else { CP_WAIT1(); }
        __syncthreads();

        if (c + 2 < NC) {
            int ws = cs + 2; if (ws >= 3) ws -= 3;
            const size_t kk0 = (size_t)(c + 2) << 5;
            const uint32_t st = sb + ws * STAGE_B;
            cpa16(st + 0 * TILE_B + so_a, Ah + ga + kk0);
            cpa16(st + 0 * TILE_B + so_b, Ah + ga + kk0 + 64 * K);
            cpa16(st + 1 * TILE_B + so_a, Al + ga + kk0);
            cpa16(st + 1 * TILE_B + so_b, Al + ga + kk0 + 64 * K);
            cpa16(st + 2 * TILE_B + so_a, Bh + gb + kk0);
            cpa16(st + 2 * TILE_B + so_b, Bh + gb + kk0 + 64 * K);
            cpa16(st + 3 * TILE_B + so_a, Bl + gb + kk0);
            cpa16(st + 3 * TILE_B + so_b, Bl + gb + kk0 + 64 * K);
            CP_COMMIT();
        }

        const uint32_t sAh = sb + cs * STAGE_B;
        const uint32_t sAl = sAh + TILE_B;
        const uint32_t sBh = sAh + 2 * TILE_B;
        const uint32_t sBl = sAh + 3 * TILE_B;

#pragma unroll
        for (int kk = 0; kk < 2; kk++) {
            const uint32_t ac16 = ac + kk * 2;
            const uint32_t bc16 = bc + kk * 2;
            uint32_t ah[2][4], al[2][4];
            ldmx4(ah[0], sAh + sw64(arow,      ac16));
            ldmx4(ah[1], sAh + sw64(arow + 16, ac16));
            ldmx4(al[0], sAl + sw64(arow,      ac16));
            ldmx4(al[1], sAl + sw64(arow + 16, ac16));
#pragma unroll
            for (int np = 0; np < 2; np++) {
                const int nt0 = 2 * np, nt1 = 2 * np + 1;
                uint32_t b0h[4], b1h[4], b0l[4], b1l[4];
                ldmx4(b0h, sBh + sw64(brow + nt0 * 16, bc16));
                ldmx4(b1h, sBh + sw64(brow + nt1 * 16, bc16));
                ldmx4(b0l, sBl + sw64(brow + nt0 * 16, bc16));
                ldmx4(b1l, sBl + sw64(brow + nt1 * 16, bc16));
                mma16816(acc[0][2 * nt0],     ah[0], b0h[0], b0h[1]);
                mma16816(acc[0][2 * nt0 + 1], ah[0], b0h[2], b0h[3]);
                mma16816(acc[1][2 * nt0],     ah[1], b0h[0], b0h[1]);
                mma16816(acc[1][2 * nt0 + 1], ah[1], b0h[2], b0h[3]);
                mma16816(acc[0][2 * nt1],     ah[0], b1h[0], b1h[1]);
                mma16816(acc[0][2 * nt1 + 1], ah[0], b1h[2], b1h[3]);
                mma16816(acc[1][2 * nt1],     ah[1], b1h[0], b1h[1]);
                mma16816(acc[1][2 * nt1 + 1], ah[1], b1h[2], b1h[3]);
                mma16816(acc[0][2 * nt0],     ah[0], b0l[0], b0l[1]);
                mma16816(acc[0][2 * nt0 + 1], ah[0], b0l[2], b0l[3]);
                mma16816(acc[1][2 * nt0],     ah[1], b0l[0], b0l[1]);
                mma16816(acc[1][2 * nt0 + 1], ah[1], b0l[2], b0l[3]);
                mma16816(acc[0][2 * nt1],     ah[0], b1l[0], b1l[1]);
                mma16816(acc[0][2 * nt1 + 1], ah[0], b1l[2], b1l[3]);
                mma16816(acc[1][2 * nt1],     ah[1], b1l[0], b1l[1]);
                mma16816(acc[1][2 * nt1 + 1], ah[1], b1l[2], b1l[3]);
                mma16816(acc[0][2 * nt0],     al[0], b0h[0], b0h[1]);
                mma16816(acc[0][2 * nt0 + 1], al[0], b0h[2], b0h[3]);
                mma16816(acc[1][2 * nt0],     al[1], b0h[0], b0h[1]);
                mma16816(acc[1][2 * nt0 + 1], al[1], b0h[2], b0h[3]);
                mma16816(acc[0][2 * nt1],     al[0], b1h[0], b1h[1]);
                mma16816(acc[0][2 * nt1 + 1], al[0], b1h[2], b1h[3]);
                mma16816(acc[1][2 * nt1],     al[1], b1h[0], b1h[1]);
                mma16816(acc[1][2 * nt1 + 1], al[1], b1h[2], b1h[3]);
            }
        }
        if (++cs >= 3) cs = 0;
    }

    const int mr = bm + wm * 32 + (lane >> 2);
    const int nc0 = bn + wn * 64 + (lane & 3) * 2;
#pragma unroll
    for (int mt = 0; mt < 2; mt++) {
#pragma unroll
        for (int n8 = 0; n8 < 8; n8++) {
            int row = mr + mt * 16;
            int col = nc0 + n8 * 8;
            *(float2*)(C + (size_t)row * N + col) =
                make_float2(acc[mt][n8][0], acc[mt][n8][1]);
            *(float2*)(C + (size_t)(row + 8) * N + col) =
                make_float2(acc[mt][n8][2], acc[mt][n8][3]);
        }
    }
}

// ---------------- warp-per-head RMSNorm+RoPE + V split ------------------------
// grid (T, 8): hh 0..5 -> 4 heads per block (warp each); hh 6..7 -> V split.
// Thread owns 4 elems (float4); RMS via shuffle tree; RoPE partner = shfl_xor 16.
__global__ __launch_bounds__(128) void norm_rope_v(
    const float* __restrict__ qkv, const int* __restrict__ pos,
    const float* __restrict__ qw,  const float* __restrict__ kw,
    __nv_bfloat16* __restrict__ qh, __nv_bfloat16* __restrict__ ql,
    __nv_bfloat16* __restrict__ kh, __nv_bfloat16* __restrict__ kl,
    __nv_bfloat16* __restrict__ vh, __nv_bfloat16* __restrict__ vl)
{
    const int t  = blockIdx.x;
    const int hh = blockIdx.y;
    const int tid = threadIdx.x;

    if (hh >= 6) {     // V split: 2 blocks x 128 threads x 4 floats = 1024
        int i = ((hh - 6) * 128 + tid) * 4;
        float4 v = *(const float4*)(qkv + (size_t)t * QKVN + QS + KVS + i);
        __nv_bfloat16 h0 = __float2bfloat16_rn(v.x);
        __nv_bfloat16 h1 = __float2bfloat16_rn(v.y);
        __nv_bfloat16 h2 = __float2bfloat16_rn(v.z);
        __nv_bfloat16 h3 = __float2bfloat16_rn(v.w);
        __nv_bfloat16 l0 = __float2bfloat16_rn(v.x - __bfloat162float(h0));
        __nv_bfloat16 l1 = __float2bfloat16_rn(v.y - __bfloat162float(h1));
        __nv_bfloat16 l2 = __float2bfloat16_rn(v.z - __bfloat162float(h2));
        __nv_bfloat16 l3 = __float2bfloat16_rn(v.w - __bfloat162float(h3));
        size_t o = (size_t)t * KVS + i;
        *(ushort4*)(vh + o) = make_ushort4(__bfloat16_as_ushort(h0), __bfloat16_as_ushort(h1),
                                           __bfloat16_as_ushort(h2), __bfloat16_as_ushort(h3));
        *(ushort4*)(vl + o) = make_ushort4(__bfloat16_as_ushort(l0), __bfloat16_as_ushort(l1),
                                           __bfloat16_as_ushort(l2), __bfloat16_as_ushort(l3));
        return;
    }

    const int wwid = tid >> 5;
    const int lane = tid & 31;
    const int head = hh * 4 + wwid;       // 0..23
    const bool isq = (head < NH);

    const float* src; const float* w;
    __nv_bfloat16* dsth; __nv_bfloat16* dstl; size_t dofs;
    if (isq) {
        src = qkv + (size_t)t * QKVN + head * HD;
        w = qw; dsth = qh; dstl = ql;
        dofs = ((size_t)t * NH + head) * HD;
    } else {
        int khd = head - NH;
        src = qkv + (size_t)t * QKVN + QS + khd * HD;
        w = kw; dsth = kh; dstl = kl;
        dofs = ((size_t)t * NKV + khd) * HD;
    }

    float4 v  = *(const float4*)(src + lane * 4);
    float4 wv = *(const float4*)(w + lane * 4);
    float ss = v.x * v.x + v.y * v.y + v.z * v.z + v.w * v.w;
#pragma unroll
    for (int o = 16; o > 0; o >>= 1)
        ss += __shfl_xor_sync(0xffffffffu, ss, o);
    float r = rsqrtf(ss * (1.f / 128.f) + 1e-6f);

    float xn[4] = {v.x * r * wv.x, v.y * r * wv.y, v.z * r * wv.z, v.w * r * wv.w};
    float oth[4];
#pragma unroll
    for (int j = 0; j < 4; j++)
        oth[j] = __shfl_xor_sync(0xffffffffu, xn[j], 16);

    const float p = (float)pos[t];
    const bool first = (lane < 16);
    const float qs = 0.088388347648318447f * 1.4426950408889634f;   // scale*log2e

    float out[4];
#pragma unroll
    for (int j = 0; j < 4; j++) {
        int i = (lane & 15) * 4 + j;
        float freq = p * exp2f((float)i * -0.2076205059304601f);
        float s, c;
        sincosf(freq, &s, &c);
        out[j] = first ? (xn[j] * c - oth[j] * s) : (xn[j] * c + oth[j] * s);
        if (isq) out[j] *= qs;
    }

    __nv_bfloat16 b0 = __float2bfloat16_rn(out[0]);
    __nv_bfloat16 b1 = __float2bfloat16_rn(out[1]);
    __nv_bfloat16 b2 = __float2bfloat16_rn(out[2]);
    __nv_bfloat16 b3 = __float2bfloat16_rn(out[3]);
    __nv_bfloat16 c0 = __float2bfloat16_rn(out[0] - __bfloat162float(b0));
    __nv_bfloat16 c1 = __float2bfloat16_rn(out[1] - __bfloat162float(b1));
    __nv_bfloat16 c2 = __float2bfloat16_rn(out[2] - __bfloat162float(b2));
    __nv_bfloat16 c3 = __float2bfloat16_rn(out[3] - __bfloat162float(b3));
    *(ushort4*)(dsth + dofs + lane * 4) =
        make_ushort4(__bfloat16_as_ushort(b0), __bfloat16_as_ushort(b1),
                     __bfloat16_as_ushort(b2), __bfloat16_as_ushort(b3));
    *(ushort4*)(dstl + dofs + lane * 4) =
        make_ushort4(__bfloat16_as_ushort(c0), __bfloat16_as_ushort(c1),
                     __bfloat16_as_ushort(c2), __bfloat16_as_ushort(c3));
}

// ---------------- HMMA flash attention: optimal LPT schedule (R16 exact) ------
#define KVT    16384
#define ASTG   (4 * KVT)
#define AQOFF  (2 * ASTG)
#define ASMEM  (3 * ASTG)
#define NITEMS 256

__global__ __launch_bounds__(256, 1) void attn_mma(
    const __nv_bfloat16* __restrict__ Qh, const __nv_bfloat16* __restrict__ Ql,
    const __nv_bfloat16* __restrict__ Kh, const __nv_bfloat16* __restrict__ Kl,
    const __nv_bfloat16* __restrict__ Vh, const __nv_bfloat16* __restrict__ Vl,
    __nv_bfloat16* __restrict__ cxh, __nv_bfloat16* __restrict__ cxl)
{
    extern __shared__ char sm[];
    const int tid = threadIdx.x;
    const int w   = tid >> 5;
    const int lane = tid & 31;
    const uint32_t sb = smem_u32(sm);
    const int cta = blockIdx.x;
    const int nit = (cta < 48) ? 1 : 2;

    const uint32_t brow0 = (uint32_t)((lane & 7) + ((lane >> 4) << 3));
    const uint32_t bcc   = (uint32_t)((lane >> 3) & 1);
    const uint32_t vrow0 = (uint32_t)(lane & 15);
    const uint32_t vb    = (uint32_t)(lane >> 4);

    for (int it = 0; it < nit; it++) {
        if (it) __syncthreads();

        const int item = (it == 0) ? cta : (303 - cta);
        const int qblk = 15 - (item >> 4);
        const int h    = item & 15;
        const int kvh  = h >> 1;
        const int q0   = qblk * 128;
        const int ntile = (q0 >> 6) + 2;

        const int sub  = tid >> 6;
        const int lrow = tid & 63;
        const __nv_bfloat16* lsrc = (sub == 0) ? Kh : (sub == 1) ? Kl
                                  : (sub == 2) ? Vh : Vl;
        const uint32_t lso = (uint32_t)(sub * KVT);
        const size_t lg = (size_t)lrow * KVS + kvh * HD;

#pragma unroll
        for (int p = 0; p < 2; p++) {
            const uint32_t st = sb + p * ASTG + lso;
            const __nv_bfloat16* g = lsrc + lg + (size_t)(p * 64) * KVS;
#pragma unroll
            for (int ci = 0; ci < 16; ci++)
                cpa16(st + swkv((uint32_t)lrow, (uint32_t)ci), g + ci * 8);
            CP_COMMIT();
        }

        {
            const int part = tid >> 7, row = tid & 127;
            const __nv_bfloat16* src = (part ? Ql : Qh) + (size_t)(q0 + row) * QS + h * HD;
            char* d = sm + AQOFF + part * 32768;
#pragma unroll
            for (int ci = 0; ci < 16; ci++)
                *(uint4*)(d + swq((uint32_t)row, (uint32_t)ci)) = *(const uint4*)(src + ci * 8);
        }
        __syncthreads();

        uint32_t qfh[8][4], qfl[8][4];
        {
            const uint32_t arow = (uint32_t)(w * 16 + (lane & 15));
#pragma unroll
            for (int kk = 0; kk < 8; kk++) {
                uint32_t c16 = (uint32_t)(lane >> 4) + kk * 2;
                ldmx4(qfh[kk], sb + AQOFF + swq(arow, c16));
                ldmx4(qfl[kk], sb + AQOFF + 32768 + swq(arow, c16));
            }
        }

        float oacc[16][4];
#pragma unroll
        for (int n = 0; n < 16; n++)
#pragma unroll
            for (int q = 0; q < 4; q++) oacc[n][q] = 0.f;
        float m0 = -1e30f, m1 = -1e30f, l0 = 0.f, l1 = 0.f;

        int cs = 0;
        for (int t0 = 0; t0 < ntile; t0++) {
            const int s0 = t0 << 6;
            if (t0 == ntile - 1) { CP_WAIT0(); } else { CP_WAIT1(); }
            __syncthreads();

            if (t0 + 2 < ntile) {
                int ws = cs + 2; if (ws >= 3) ws -= 3;
                const uint32_t st = sb + ws * ASTG + lso;
                const __nv_bfloat16* g = lsrc + lg + (size_t)((t0 + 2) * 64) * KVS;
#pragma unroll
                for (int ci = 0; ci < 16; ci++)
                    cpa16(st + swkv((uint32_t)lrow, (uint32_t)ci), g + ci * 8);
                CP_COMMIT();
            }

            const uint32_t sKh = sb + cs * ASTG;
            const uint32_t sKl = sKh + KVT;
            const uint32_t sVh = sKh + 2 * KVT;
            const uint32_t sVl = sKh + 3 * KVT;

            float sacc[8][4];
#pragma unroll
            for (int t = 0; t < 8; t++)
#pragma unroll
                for (int q = 0; q < 4; q++) sacc[t][q] = 0.f;

#pragma unroll
            for (int kk = 0; kk < 8; kk++) {
                const uint32_t kc = bcc + kk * 2;
                uint32_t bh[4][4], bl[4][4];
#pragma unroll
                for (int nt = 0; nt < 4; nt++) {
                    ldmx4(bh[nt], sKh + swkv(brow0 + nt * 16, kc));
                    ldmx4(bl[nt], sKl + swkv(brow0 + nt * 16, kc));
                }
#pragma unroll
                for (int nt = 0; nt < 4; nt++) {
                    mma16816(sacc[2 * nt],     qfh[kk], bh[nt][0], bh[nt][1]);
                    mma16816(sacc[2 * nt + 1], qfh[kk], bh[nt][2], bh[nt][3]);
                }
#pragma unroll
                for (int nt = 0; nt < 4; nt++) {
                    mma16816(sacc[2 * nt],     qfh[kk], bl[nt][0], bl[nt][1]);
                    mma16816(sacc[2 * nt + 1], qfh[kk], bl[nt][2], bl[nt][3]);
                }
#pragma unroll
                for (int nt = 0; nt < 4; nt++) {
                    mma16816(sacc[2 * nt],     qfl[kk], bh[nt][0], bh[nt][1]);
                    mma16816(sacc[2 * nt + 1], qfl[kk], bh[nt][2], bh[nt][3]);
                }
            }

            const int qr0 = q0 + w * 16 + (lane >> 2);
            const int qr1 = qr0 + 8;
            const bool domask = (s0 + 63 > q0 + w * 16);
            float mt0 = -1e30f, mt1 = -1e30f;
#pragma unroll
            for (int t = 0; t < 8; t++) {
                float v0 = sacc[t][0], v1 = sacc[t][1];
                float v2 = sacc[t][2], v3 = sacc[t][3];
                if (domask) {
                    int c = s0 + t * 8 + (lane & 3) * 2;
                    if (c     > qr0) v0 = -1e30f;
                    if (c + 1 > qr0) v1 = -1e30f;
                    if (c     > qr1) v2 = -1e30f;
                    if (c + 1 > qr1) v3 = -1e30f;
                    sacc[t][0] = v0; sacc[t][1] = v1; sacc[t][2] = v2; sacc[t][3] = v3;
                }
                mt0 = fmaxf(mt0, fmaxf(v0, v1));
                mt1 = fmaxf(mt1, fmaxf(v2, v3));
            }
            mt0 = fmaxf(mt0, __shfl_xor_sync(0xffffffffu, mt0, 1));
            mt0 = fmaxf(mt0, __shfl_xor_sync(0xffffffffu, mt0, 2));
            mt1 = fmaxf(mt1, __shfl_xor_sync(0xffffffffu, mt1, 1));
            mt1 = fmaxf(mt1, __shfl_xor_sync(0xffffffffu, mt1, 2));
            float mn0 = fmaxf(m0, mt0), mn1 = fmaxf(m1, mt1);
            float f0 = ex2f(m0 - mn0), f1 = ex2f(m1 - mn1);
            m0 = mn0; m1 = mn1;

            float ls0 = 0.f, ls1 = 0.f;
#pragma unroll
            for (int t = 0; t < 8; t++) {
                sacc[t][0] = ex2f(sacc[t][0] - mn0);
                sacc[t][1] = ex2f(sacc[t][1] - mn0);
                sacc[t][2] = ex2f(sacc[t][2] - mn1);
                sacc[t][3] = ex2f(sacc[t][3] - mn1);
                ls0 += sacc[t][0] + sacc[t][1];
                ls1 += sacc[t][2] + sacc[t][3];
            }
            ls0 += __shfl_xor_sync(0xffffffffu, ls0, 1);
            ls0 += __shfl_xor_sync(0xffffffffu, ls0, 2);
            ls1 += __shfl_xor_sync(0xffffffffu, ls1, 1);
            ls1 += __shfl_xor_sync(0xffffffffu, ls1, 2);
            l0 = l0 * f0 + ls0;
            l1 = l1 * f1 + ls1;
#pragma unroll
            for (int n = 0; n < 16; n++) {
                oacc[n][0] *= f0; oacc[n][1] *= f0;
                oacc[n][2] *= f1; oacc[n][3] *= f1;
            }

#pragma unroll
            for (int ks = 0; ks < 4; ks++) {
                uint32_t pah[4], pal[4];
#pragma unroll
                for (int half = 0; half < 2; half++) {
                    float x0 = sacc[2 * ks + half][0], x1 = sacc[2 * ks + half][1];
                    float x2 = sacc[2 * ks + half][2], x3 = sacc[2 * ks + half][3];
                    uint32_t h01 = packbf(x0, x1);
                    uint32_t h23 = packbf(x2, x3);
                    pah[2 * half]     = h01;
                    pah[2 * half + 1] = h23;
                    float h0f = __uint_as_float(h01 << 16);
                    float h1f = __uint_as_float(h01 & 0xffff0000u);
                    float h2f = __uint_as_float(h23 << 16);
                    float h3f = __uint_as_float(h23 & 0xffff0000u);
                    pal[2 * half]     = packbf(x0 - h0f, x1 - h1f);
                    pal[2 * half + 1] = packbf(x2 - h2f, x3 - h3f);
                }
#pragma unroll
                for (int np = 0; np < 4; np++) {
                    const int nt = 2 * np;
                    const uint32_t r = vrow0 + ks * 16;
                    uint32_t vha[4], vla[4], vhb[4], vlb[4];
                    ldmx4t(vha, sVh + swkv(r, vb + nt * 2));
                    ldmx4t(vla, sVl + swkv(r, vb + nt * 2));
                    ldmx4t(vhb, sVh + swkv(r, vb + (nt + 1) * 2));
                    ldmx4t(vlb, sVl + swkv(r, vb + (nt + 1) * 2));
                    mma16816(oacc[2 * nt],     pah, vha[0], vha[1]);
                    mma16816(oacc[2 * nt + 1], pah, vha[2], vha[3]);
                    mma16816(oacc[2 * nt + 2], pah, vhb[0], vhb[1]);
                    mma16816(oacc[2 * nt + 3], pah, vhb[2], vhb[3]);
                    mma16816(oacc[2 * nt],     pah, vla[0], vla[1]);
                    mma16816(oacc[2 * nt + 1], pah, vla[2], vla[3]);
                    mma16816(oacc[2 * nt + 2], pah, vlb[0], vlb[1]);
                    mma16816(oacc[2 * nt + 3], pah, vlb[2], vlb[3]);
                    mma16816(oacc[2 * nt],     pal, vha[0], vha[1]);
                    mma16816(oacc[2 * nt + 1], pal, vha[2], vha[3]);
                    mma16816(oacc[2 * nt + 2], pal, vhb[0], vhb[1]);
                    mma16816(oacc[2 * nt + 3], pal, vhb[2], vhb[3]);
                }
            }
            if (++cs >= 3) cs = 0;
        }

        float il0 = 1.f / l0, il1 = 1.f / l1;
        const int row0 = q0 + w * 16 + (lane >> 2);
#pragma unroll
        for (int n = 0; n < 16; n++) {
            int col = h * HD + n * 8 + (lane & 3) * 2;
            float o0 = oacc[n][0] * il0, o1 = oacc[n][1] * il0;
            float o2 = oacc[n][2] * il1, o3 = oacc[n][3] * il1;
            uint32_t hi01 = packbf(o0, o1);
            uint32_t hi23 = packbf(o2, o3);
            float h0f = __uint_as_float(hi01 << 16);
            float h1f = __uint_as_float(hi01 & 0xffff0000u);
            float h2f = __uint_as_float(hi23 << 16);
            float h3f = __uint_as_float(hi23 & 0xffff0000u);
            uint32_t lo01 = packbf(o0 - h0f, o1 - h1f);
            uint32_t lo23 = packbf(o2 - h2f, o3 - h3f);
            *(uint32_t*)(cxh + (size_t)row0 * QS + col)       = hi01;
            *(uint32_t*)(cxl + (size_t)row0 * QS + col)       = lo01;
            *(uint32_t*)(cxh + (size_t)(row0 + 8) * QS + col) = hi23;
            *(uint32_t*)(cxl + (size_t)(row0 + 8) * QS + col) = lo23;
        }
    }
}

// ============================================================
extern "C" void kernel_launch(void* const* d_in, const int* in_sizes, int n_in,
                              void* d_out, int out_size)
{
    const int*   positions = (const int*)d_in[0];
    const float* hidden    = (const float*)d_in[1];
    const float* qkv_w     = (const float*)d_in[2];
    const float* q_norm_w  = (const float*)d_in[3];
    const float* k_norm_w  = (const float*)d_in[4];
    const float* o_w       = (const float*)d_in[5];
    float* out = (float*)d_out;

    float* qkv;
    cudaGetSymbolAddress((void**)&qkv, g_qkv);
    __nv_bfloat16 *hid_h, *hid_l, *qw_h, *qw_l, *ow_h, *ow_l, *cx_h, *cx_l;
    __nv_bfloat16 *qh, *ql, *kh, *kl, *vh, *vl;
    cudaGetSymbolAddress((void**)&hid_h, g_hid_h);
    cudaGetSymbolAddress((void**)&hid_l, g_hid_l);
    cudaGetSymbolAddress((void**)&qw_h,  g_qkvw_h);
    cudaGetSymbolAddress((void**)&qw_l,  g_qkvw_l);
    cudaGetSymbolAddress((void**)&ow_h,  g_ow_h);
    cudaGetSymbolAddress((void**)&ow_l,  g_ow_l);
    cudaGetSymbolAddress((void**)&cx_h,  g_ctx_h);
    cudaGetSymbolAddress((void**)&cx_l,  g_ctx_l);
    cudaGetSymbolAddress((void**)&qh, g_qh);
    cudaGetSymbolAddress((void**)&ql, g_ql);
    cudaGetSymbolAddress((void**)&kh, g_kh);
    cudaGetSymbolAddress((void**)&kl, g_kl);
    cudaGetSymbolAddress((void**)&vh, g_vh);
    cudaGetSymbolAddress((void**)&vl, g_vl);

    cudaFuncSetAttribute(gemm_mma, cudaFuncAttributeMaxDynamicSharedMemorySize, DSMEM_B);
    cudaFuncSetAttribute(attn_mma, cudaFuncAttributeMaxDynamicSharedMemorySize, ASMEM);

    // 0) fused fp32 -> bf16 hi/lo splits
    split_all<<<(N4_HID + N4_QW + N4_OW + 255) / 256, 256>>>(
        hidden, qkv_w, o_w, hid_h, hid_l, qw_h, qw_l, ow_h, ow_l);

    // 1) QKV projection
    gemm_mma<<<dim3(QKVN / 128, TT / 128), 256, DSMEM_B>>>(
        hid_h, hid_l, qw_h, qw_l, qkv, TT, QKVN, HID);

    // 2) warp-per-head RMSNorm+RoPE (Q pre-scaled by scale*log2e) + V split
    norm_rope_v<<<dim3(TT, 8), 128>>>(
        qkv, positions, q_norm_w, k_norm_w, qh, ql, kh, kl, vh, vl);

    // 3) causal GQA flash attention (optimal LPT: 48 singles + 104 exact-28 pairs)
    attn_mma<<<NSM, 256, ASMEM>>>(qh, ql, kh, kl, vh, vl, cx_h, cx_l);

    // 4) O projection
    gemm_mma<<<dim3(HID / 128, TT / 128), 256, DSMEM_B>>>(
        cx_h, cx_l, ow_h, ow_l, out, TT, HID, QS);
}